// round 11
// baseline (speedup 1.0000x reference)
#include <cuda_runtime.h>
#include <math.h>
#include <stdint.h>

#define N_TOK 2304
#define CC    256
#define HEADS 8
#define DH    64
#define INNER 512
#define BATCH 4

// Scratch (device globals; no runtime allocation allowed)
__device__ float g_q[(size_t)BATCH*HEADS*N_TOK*DH]; // [b][h][n][d]  l2norm'd * 10, tf32-rounded
__device__ float g_k[(size_t)BATCH*HEADS*N_TOK*DH]; // [b][h][n][d]  l2norm'd, tf32-rounded
__device__ float g_v[(size_t)BATCH*HEADS*N_TOK*DH]; // [b][h][n][d]  tf32-rounded
__device__ float g_o[(size_t)BATCH*INNER*N_TOK];    // [b][ci][n]

__device__ __forceinline__ float tf32r(float x) {
    uint32_t u; asm("cvt.rna.tf32.f32 %0, %1;" : "=r"(u) : "f"(x));
    return __uint_as_float(u);
}

// Warp-level tf32 MMA: D(16x8) += A(16x8) * B(8x8), row.col
__device__ __forceinline__ void mma_tf32(float c[4],
                                         uint32_t a0, uint32_t a1, uint32_t a2, uint32_t a3,
                                         uint32_t b0, uint32_t b1) {
    asm volatile(
        "mma.sync.aligned.m16n8k8.row.col.f32.tf32.tf32.f32 "
        "{%0,%1,%2,%3}, {%4,%5,%6,%7}, {%8,%9}, {%0,%1,%2,%3};"
        : "+f"(c[0]), "+f"(c[1]), "+f"(c[2]), "+f"(c[3])
        : "r"(a0), "r"(a1), "r"(a2), "r"(a3), "r"(b0), "r"(b1));
}

// pair-permute within each group of 8: logical c -> (c&~7) + (c&3)*2 + ((c>>2)&1)
// so logical (cl, cl+4) land at adjacent positions (2cl, 2cl+1) -> one LDS.64
__device__ __forceinline__ int phi(int c) {
    return (c & ~7) + ((c & 3) << 1) + ((c >> 2) & 1);
}

// ---------------------------------------------------------------------------
// Kernel A (fp32 FFMA, at roofline): QKV projection GEMM with fused l2norm
// (+SCALE on Q), tf32 rounding ONLY at the final store. Q,K,V -> [b][h][n][d].
// ---------------------------------------------------------------------------
__global__ __launch_bounds__(256) void qkv_kernel(const float* __restrict__ x,
                                                  const float* __restrict__ wqkv) {
    const int nt = blockIdx.x;
    const int ot = blockIdx.y;
    const int b  = blockIdx.z;
    const int n0 = nt * 64;
    const int o0 = ot * 64;
    const int p  = ot >> 3;
    const int h  = ot & 7;

    __shared__ float sX[16][64];
    __shared__ float sW[16][68];

    const int t  = threadIdx.x;
    const int ty = t >> 4;   // n sub-index
    const int tx = t & 15;   // d sub-index

    float acc[4][4] = {};
    const float* xb = x + (size_t)b * CC * N_TOK;

    for (int c0 = 0; c0 < CC; c0 += 16) {
        {
            int kk = t >> 4, nn = (t & 15) * 4;
            *(float4*)&sX[kk][nn] = *(const float4*)&xb[(size_t)(c0 + kk) * N_TOK + n0 + nn];
        }
        {
            int oo = t >> 2, k4 = (t & 3) * 4;
            float4 w4 = *(const float4*)&wqkv[(size_t)(o0 + oo) * CC + c0 + k4];
            sW[k4 + 0][oo] = w4.x; sW[k4 + 1][oo] = w4.y;
            sW[k4 + 2][oo] = w4.z; sW[k4 + 3][oo] = w4.w;
        }
        __syncthreads();
#pragma unroll
        for (int kk = 0; kk < 16; kk++) {
            float4 a4 = *(float4*)&sX[kk][ty * 4];
            float4 b4 = *(float4*)&sW[kk][tx * 4];
            float a[4] = {a4.x, a4.y, a4.z, a4.w};
            float bb[4] = {b4.x, b4.y, b4.z, b4.w};
#pragma unroll
            for (int i = 0; i < 4; i++)
#pragma unroll
                for (int j = 0; j < 4; j++)
                    acc[i][j] += a[i] * bb[j];
        }
        __syncthreads();
    }

    const int bh = b * HEADS + h;

    if (p == 2) {
        // V: write [n][d] directly, tf32-rounded, coalesced
        float* dst = g_v + ((size_t)bh * N_TOK + n0) * DH;
#pragma unroll
        for (int i = 0; i < 4; i++) {
            float4 v4 = make_float4(tf32r(acc[i][0]), tf32r(acc[i][1]),
                                    tf32r(acc[i][2]), tf32r(acc[i][3]));
            *(float4*)&dst[(size_t)(ty * 4 + i) * DH + tx * 4] = v4;
        }
    } else {
        // Q/K: l2-normalize rows (d spread across 16-lane tx group)
        float ssq[4];
#pragma unroll
        for (int i = 0; i < 4; i++)
            ssq[i] = acc[i][0] * acc[i][0] + acc[i][1] * acc[i][1] +
                     acc[i][2] * acc[i][2] + acc[i][3] * acc[i][3];
#pragma unroll
        for (int off = 8; off; off >>= 1)
#pragma unroll
            for (int i = 0; i < 4; i++)
                ssq[i] += __shfl_xor_sync(0xffffffffu, ssq[i], off);

        const float sf = (p == 0) ? 10.0f : 1.0f;   // fold SCALE into Q
        float* dst = (p == 0 ? g_q : g_k) + ((size_t)bh * N_TOK + n0) * DH;
#pragma unroll
        for (int i = 0; i < 4; i++) {
            float inv = sf / fmaxf(sqrtf(ssq[i]), 1e-12f);
            float4 v4 = make_float4(tf32r(acc[i][0] * inv), tf32r(acc[i][1] * inv),
                                    tf32r(acc[i][2] * inv), tf32r(acc[i][3] * inv));
            *(float4*)&dst[(size_t)(ty * 4 + i) * DH + tx * 4] = v4;
        }
    }
}

// ---------------------------------------------------------------------------
// Kernel B: tf32 mma.sync flash attention with pair-permuted smem + prefetch.
// CTA = 128 q rows, 8 warps x 16 rows. kv-tiles of 64.
// Fixed softmax max SCALE=10; O accumulates in regs across all kv-tiles.
// ---------------------------------------------------------------------------
#define PADK 72
#define PADP 68
#define SK_OFF 0
#define SV_OFF (64 * PADK)
#define SP_OFF (2 * 64 * PADK)
#define ATT_SMEM_FLOATS (2 * 64 * PADK + 128 * PADP)
#define NKT (N_TOK / 64)

extern __shared__ float att_smem[];
__global__ __launch_bounds__(256, 2) void attn_mma_kernel() {
    float* sK  = att_smem + SK_OFF;   // [64 kv][PADK]  d-cols pair-permuted
    float* sVT = att_smem + SV_OFF;   // [64 d][PADK]   kv-cols pair-permuted
    float* sP  = att_smem + SP_OFF;   // [128][PADP]    Q staging / P / O staging

    const int t    = threadIdx.x;
    const int lane = t & 31;
    const int wid  = t >> 5;
    const int qt   = blockIdx.x;
    const int h    = blockIdx.y;
    const int b    = blockIdx.z;
    const int bh   = b * HEADS + h;
    const int n0   = qt * 128;

    const int r  = lane >> 2;
    const int cl = lane & 3;
    const int qrow = wid * 16 + r;

    // loader coords
    const int kvr = t >> 2;          // 0..63
    const int cb  = (t & 3) * 16;
    const int pkv = phi(kvr);
    const float* Kgb = g_k + ((size_t)bh * N_TOK + kvr) * DH + cb;
    const float* Vgb = g_v + ((size_t)bh * N_TOK + kvr) * DH + cb;

    // ---- Stage Q tile (128 x 64) into sP ----
    {
        int row = t >> 1, cc = (t & 1) * 32;
        const float* Qg = g_q + ((size_t)bh * N_TOK + n0 + row) * DH + cc;
#pragma unroll
        for (int c = 0; c < 8; c++)
            *(float4*)&sP[row * PADP + cc + c * 4] = *(const float4*)&Qg[c * 4];
    }

    // prefetch tile 0 into regs
    float4 kreg[4], vreg[4];
#pragma unroll
    for (int c4 = 0; c4 < 4; c4++) {
        kreg[c4] = *(const float4*)&Kgb[c4 * 4];
        vreg[c4] = *(const float4*)&Vgb[c4 * 4];
    }
    __syncthreads();

    // extract Q A-fragments (once)
    uint32_t qa[8][4];
#pragma unroll
    for (int k = 0; k < 8; k++) {
        qa[k][0] = __float_as_uint(sP[qrow * PADP + k * 8 + cl]);
        qa[k][1] = __float_as_uint(sP[(qrow + 8) * PADP + k * 8 + cl]);
        qa[k][2] = __float_as_uint(sP[qrow * PADP + k * 8 + cl + 4]);
        qa[k][3] = __float_as_uint(sP[(qrow + 8) * PADP + k * 8 + cl + 4]);
    }
    // store tile 0 (permuted)
    {
        float* kd = sK + kvr * PADK;
#pragma unroll
        for (int c4 = 0; c4 < 4; c4++) {
            int c = cb + c4 * 4;
            float4 v = kreg[c4];
            kd[phi(c + 0)] = v.x; kd[phi(c + 1)] = v.y;
            kd[phi(c + 2)] = v.z; kd[phi(c + 3)] = v.w;
            float4 w = vreg[c4];
            sVT[(c + 0) * PADK + pkv] = w.x; sVT[(c + 1) * PADK + pkv] = w.y;
            sVT[(c + 2) * PADK + pkv] = w.z; sVT[(c + 3) * PADK + pkv] = w.w;
        }
    }
    __syncthreads();

    float o[8][4] = {};
    float l0 = 0.0f, l1 = 0.0f;

    for (int it = 0; it < NKT; it++) {
        // ---- S = Q . K^T : per warp 16 x 64 ----
        float s[8][4];
#pragma unroll
        for (int nb = 0; nb < 8; nb++) {
            s[nb][0] = s[nb][1] = s[nb][2] = s[nb][3] = 0.0f;
#pragma unroll
            for (int kb = 0; kb < 8; kb++) {
                float2 bb = *(float2*)&sK[(nb * 8 + r) * PADK + kb * 8 + cl * 2];
                mma_tf32(s[nb], qa[kb][0], qa[kb][1], qa[kb][2], qa[kb][3],
                         __float_as_uint(bb.x), __float_as_uint(bb.y));
            }
        }

        // ---- p = exp(s - 10); row sums; P -> sP (tf32, own warp rows) ----
#pragma unroll
        for (int nb = 0; nb < 8; nb++) {
            float p0 = __expf(s[nb][0] - 10.0f);
            float p1 = __expf(s[nb][1] - 10.0f);
            float p2 = __expf(s[nb][2] - 10.0f);
            float p3 = __expf(s[nb][3] - 10.0f);
            l0 += p0 + p1;
            l1 += p2 + p3;
            *(float2*)&sP[qrow * PADP + nb * 8 + 2 * cl] =
                make_float2(tf32r(p0), tf32r(p1));
            *(float2*)&sP[(qrow + 8) * PADP + nb * 8 + 2 * cl] =
                make_float2(tf32r(p2), tf32r(p3));
        }

        // ---- prefetch next tile (global -> regs), hidden under PV ----
        if (it < NKT - 1) {
            const float* Kg = Kgb + (size_t)(it + 1) * 64 * DH;
            const float* Vg = Vgb + (size_t)(it + 1) * 64 * DH;
#pragma unroll
            for (int c4 = 0; c4 < 4; c4++) {
                kreg[c4] = *(const float4*)&Kg[c4 * 4];
                vreg[c4] = *(const float4*)&Vg[c4 * 4];
            }
        }

        // ---- O += P . V : per warp 16 x 64 ----
#pragma unroll
        for (int kb = 0; kb < 8; kb++) {
            uint32_t a0 = __float_as_uint(sP[qrow * PADP + kb * 8 + cl]);
            uint32_t a1 = __float_as_uint(sP[(qrow + 8) * PADP + kb * 8 + cl]);
            uint32_t a2 = __float_as_uint(sP[qrow * PADP + kb * 8 + cl + 4]);
            uint32_t a3 = __float_as_uint(sP[(qrow + 8) * PADP + kb * 8 + cl + 4]);
#pragma unroll
            for (int nb = 0; nb < 8; nb++) {
                float2 bb = *(float2*)&sVT[(nb * 8 + r) * PADK + kb * 8 + cl * 2];
                mma_tf32(o[nb], a0, a1, a2, a3,
                         __float_as_uint(bb.x), __float_as_uint(bb.y));
            }
        }

        __syncthreads();   // all warps done reading sK/sVT
        if (it < NKT - 1) {
            float* kd = sK + kvr * PADK;
#pragma unroll
            for (int c4 = 0; c4 < 4; c4++) {
                int c = cb + c4 * 4;
                float4 v = kreg[c4];
                kd[phi(c + 0)] = v.x; kd[phi(c + 1)] = v.y;
                kd[phi(c + 2)] = v.z; kd[phi(c + 3)] = v.w;
                float4 w = vreg[c4];
                sVT[(c + 0) * PADK + pkv] = w.x; sVT[(c + 1) * PADK + pkv] = w.y;
                sVT[(c + 2) * PADK + pkv] = w.z; sVT[(c + 3) * PADK + pkv] = w.w;
            }
        }
        __syncthreads();   // next tile ready
    }

    // ---- finalize row sums (quad reduce) and normalize ----
    l0 += __shfl_xor_sync(0xffffffffu, l0, 1);
    l0 += __shfl_xor_sync(0xffffffffu, l0, 2);
    l1 += __shfl_xor_sync(0xffffffffu, l1, 1);
    l1 += __shfl_xor_sync(0xffffffffu, l1, 2);
    const float inv0 = 1.0f / l0;
    const float inv1 = 1.0f / l1;

#pragma unroll
    for (int nb = 0; nb < 8; nb++) {
        *(float2*)&sP[qrow * PADP + nb * 8 + 2 * cl] =
            make_float2(o[nb][0] * inv0, o[nb][1] * inv0);
        *(float2*)&sP[(qrow + 8) * PADP + nb * 8 + 2 * cl] =
            make_float2(o[nb][2] * inv1, o[nb][3] * inv1);
    }
    __syncthreads();

    // transposed write: g_o[bh*DH + d][n0 + q]
    {
        const int d  = t >> 2;
        const int qc = (t & 3) * 32;
        float* Ob = g_o + ((size_t)bh * DH + d) * N_TOK + n0 + qc;
#pragma unroll
        for (int i = 0; i < 8; i++) {
            int q = qc + i * 4;
            float4 v4 = make_float4(sP[(q + 0) * PADP + d], sP[(q + 1) * PADP + d],
                                    sP[(q + 2) * PADP + d], sP[(q + 3) * PADP + d]);
            *(float4*)&Ob[i * 4] = v4;
        }
    }
}

// ---------------------------------------------------------------------------
// Kernel C (fp32 FFMA): output projection
// out[b,o,n] = sum_ci wout[o,ci]*g_o[b,ci,n] + bias
// ---------------------------------------------------------------------------
__global__ __launch_bounds__(256) void out_kernel(const float* __restrict__ wout,
                                                  const float* __restrict__ bias,
                                                  float* __restrict__ out) {
    const int nt = blockIdx.x;
    const int ot = blockIdx.y;
    const int b  = blockIdx.z;
    const int n0 = nt * 64;
    const int o0 = ot * 64;

    __shared__ float sG[16][64];
    __shared__ float sW[16][68];

    const int t  = threadIdx.x;
    const int ty = t >> 4;
    const int tx = t & 15;

    float acc[4][4] = {};
    const float* gb = g_o + (size_t)b * INNER * N_TOK;

    for (int c0 = 0; c0 < INNER; c0 += 16) {
        {
            int kk = t >> 4, nn = (t & 15) * 4;
            *(float4*)&sG[kk][nn] = *(const float4*)&gb[(size_t)(c0 + kk) * N_TOK + n0 + nn];
        }
        {
            int oo = t >> 2, k4 = (t & 3) * 4;
            float4 w4 = *(const float4*)&wout[(size_t)(o0 + oo) * INNER + c0 + k4];
            sW[k4 + 0][oo] = w4.x; sW[k4 + 1][oo] = w4.y;
            sW[k4 + 2][oo] = w4.z; sW[k4 + 3][oo] = w4.w;
        }
        __syncthreads();
#pragma unroll
        for (int kk = 0; kk < 16; kk++) {
            float4 a4 = *(float4*)&sW[kk][ty * 4];
            float4 b4 = *(float4*)&sG[kk][tx * 4];
            float a[4] = {a4.x, a4.y, a4.z, a4.w};
            float bb[4] = {b4.x, b4.y, b4.z, b4.w};
#pragma unroll
            for (int i = 0; i < 4; i++)
#pragma unroll
                for (int j = 0; j < 4; j++)
                    acc[i][j] += a[i] * bb[j];
        }
        __syncthreads();
    }

    float* ob = out + ((size_t)b * CC + o0) * N_TOK;
#pragma unroll
    for (int i = 0; i < 4; i++) {
        float bi = bias[o0 + ty * 4 + i];
        float4 v4 = make_float4(acc[i][0] + bi, acc[i][1] + bi,
                                acc[i][2] + bi, acc[i][3] + bi);
        *(float4*)&ob[(size_t)(ty * 4 + i) * N_TOK + n0 + tx * 4] = v4;
    }
}

// ---------------------------------------------------------------------------
extern "C" void kernel_launch(void* const* d_in, const int* in_sizes, int n_in,
                              void* d_out, int out_size) {
    const float* x    = (const float*)d_in[0];
    const float* wqkv = (const float*)d_in[1];
    const float* wout = (const float*)d_in[2];
    const float* bout = (const float*)d_in[3];
    float* out = (float*)d_out;

    (void)in_sizes; (void)n_in; (void)out_size;

    cudaFuncSetAttribute(attn_mma_kernel, cudaFuncAttributeMaxDynamicSharedMemorySize,
                         ATT_SMEM_FLOATS * sizeof(float));

    qkv_kernel<<<dim3(36, 24, 4), 256>>>(x, wqkv);
    attn_mma_kernel<<<dim3(18, 8, 4), 256, ATT_SMEM_FLOATS * sizeof(float)>>>();
    out_kernel<<<dim3(36, 4, 4), 256>>>(wout, bout, out);
}

// round 12
// speedup vs baseline: 1.2401x; 1.2401x over previous
#include <cuda_runtime.h>
#include <math.h>
#include <stdint.h>

#define N_TOK 2304
#define CC    256
#define HEADS 8
#define DH    64
#define INNER 512
#define BATCH 4

// Scratch (device globals; no runtime allocation allowed)
__device__ float g_q[(size_t)BATCH*HEADS*N_TOK*DH]; // [b][h][n][d]  l2norm'd * 10, tf32-rounded
__device__ float g_k[(size_t)BATCH*HEADS*N_TOK*DH]; // [b][h][n][d]  l2norm'd, tf32-rounded
__device__ float g_v[(size_t)BATCH*HEADS*N_TOK*DH]; // [b][h][n][d]  tf32-rounded
__device__ float g_o[(size_t)BATCH*INNER*N_TOK];    // [b][ci][n]

__device__ __forceinline__ float tf32r(float x) {
    uint32_t u; asm("cvt.rna.tf32.f32 %0, %1;" : "=r"(u) : "f"(x));
    return __uint_as_float(u);
}
__device__ __forceinline__ uint32_t smem_u32(const void* p) {
    uint32_t a;
    asm("{ .reg .u64 t; cvta.to.shared.u64 t, %1; cvt.u32.u64 %0, t; }" : "=r"(a) : "l"(p));
    return a;
}
__device__ __forceinline__ void cp16(uint32_t dst, const void* src) {
    asm volatile("cp.async.cg.shared.global [%0], [%1], 16;" :: "r"(dst), "l"(src) : "memory");
}
#define CP_COMMIT() asm volatile("cp.async.commit_group;" ::: "memory")
#define CP_WAIT0()  asm volatile("cp.async.wait_group 0;" ::: "memory")

// Warp-level tf32 MMA: D(16x8) += A(16x8) * B(8x8), row.col
__device__ __forceinline__ void mma_tf32(float c[4],
                                         uint32_t a0, uint32_t a1, uint32_t a2, uint32_t a3,
                                         uint32_t b0, uint32_t b1) {
    asm volatile(
        "mma.sync.aligned.m16n8k8.row.col.f32.tf32.tf32.f32 "
        "{%0,%1,%2,%3}, {%4,%5,%6,%7}, {%8,%9}, {%0,%1,%2,%3};"
        : "+f"(c[0]), "+f"(c[1]), "+f"(c[2]), "+f"(c[3])
        : "r"(a0), "r"(a1), "r"(a2), "r"(a3), "r"(b0), "r"(b1));
}

// ---------------------------------------------------------------------------
// Kernel A (fp32 FFMA, at roofline): QKV projection GEMM with fused l2norm
// (+SCALE on Q), tf32 rounding ONLY at the final store. Q,K,V -> [b][h][n][d].
// ---------------------------------------------------------------------------
__global__ __launch_bounds__(256) void qkv_kernel(const float* __restrict__ x,
                                                  const float* __restrict__ wqkv) {
    const int nt = blockIdx.x;
    const int ot = blockIdx.y;
    const int b  = blockIdx.z;
    const int n0 = nt * 64;
    const int o0 = ot * 64;
    const int p  = ot >> 3;
    const int h  = ot & 7;

    __shared__ float sX[16][64];
    __shared__ float sW[16][68];

    const int t  = threadIdx.x;
    const int ty = t >> 4;   // n sub-index
    const int tx = t & 15;   // d sub-index

    float acc[4][4] = {};
    const float* xb = x + (size_t)b * CC * N_TOK;

    for (int c0 = 0; c0 < CC; c0 += 16) {
        {
            int kk = t >> 4, nn = (t & 15) * 4;
            *(float4*)&sX[kk][nn] = *(const float4*)&xb[(size_t)(c0 + kk) * N_TOK + n0 + nn];
        }
        {
            int oo = t >> 2, k4 = (t & 3) * 4;
            float4 w4 = *(const float4*)&wqkv[(size_t)(o0 + oo) * CC + c0 + k4];
            sW[k4 + 0][oo] = w4.x; sW[k4 + 1][oo] = w4.y;
            sW[k4 + 2][oo] = w4.z; sW[k4 + 3][oo] = w4.w;
        }
        __syncthreads();
#pragma unroll
        for (int kk = 0; kk < 16; kk++) {
            float4 a4 = *(float4*)&sX[kk][ty * 4];
            float4 b4 = *(float4*)&sW[kk][tx * 4];
            float a[4] = {a4.x, a4.y, a4.z, a4.w};
            float bb[4] = {b4.x, b4.y, b4.z, b4.w};
#pragma unroll
            for (int i = 0; i < 4; i++)
#pragma unroll
                for (int j = 0; j < 4; j++)
                    acc[i][j] += a[i] * bb[j];
        }
        __syncthreads();
    }

    const int bh = b * HEADS + h;

    if (p == 2) {
        float* dst = g_v + ((size_t)bh * N_TOK + n0) * DH;
#pragma unroll
        for (int i = 0; i < 4; i++) {
            float4 v4 = make_float4(tf32r(acc[i][0]), tf32r(acc[i][1]),
                                    tf32r(acc[i][2]), tf32r(acc[i][3]));
            *(float4*)&dst[(size_t)(ty * 4 + i) * DH + tx * 4] = v4;
        }
    } else {
        float ssq[4];
#pragma unroll
        for (int i = 0; i < 4; i++)
            ssq[i] = acc[i][0] * acc[i][0] + acc[i][1] * acc[i][1] +
                     acc[i][2] * acc[i][2] + acc[i][3] * acc[i][3];
#pragma unroll
        for (int off = 8; off; off >>= 1)
#pragma unroll
            for (int i = 0; i < 4; i++)
                ssq[i] += __shfl_xor_sync(0xffffffffu, ssq[i], off);

        const float sf = (p == 0) ? 10.0f : 1.0f;   // fold SCALE into Q
        float* dst = (p == 0 ? g_q : g_k) + ((size_t)bh * N_TOK + n0) * DH;
#pragma unroll
        for (int i = 0; i < 4; i++) {
            float inv = sf / fmaxf(sqrtf(ssq[i]), 1e-12f);
            float4 v4 = make_float4(tf32r(acc[i][0] * inv), tf32r(acc[i][1] * inv),
                                    tf32r(acc[i][2] * inv), tf32r(acc[i][3] * inv));
            *(float4*)&dst[(size_t)(ty * 4 + i) * DH + tx * 4] = v4;
        }
    }
}

// ---------------------------------------------------------------------------
// Kernel B: tf32 mma.sync flash attention, cp.async double-buffered K/V.
// CTA = 128 q rows, 8 warps x 16 rows. kv-tiles of 64, one barrier per tile.
// Fixed softmax max SCALE=10; O accumulates in regs across all kv-tiles.
// ---------------------------------------------------------------------------
#define PADK 68
#define PADV 72
#define PADP 68
#define KBUF (64 * PADK)
#define VBUF (64 * PADV)
#define SK0  0
#define SK1  KBUF
#define SV0  (2 * KBUF)
#define SV1  (2 * KBUF + VBUF)
#define SPO  (2 * KBUF + 2 * VBUF)
#define ATT_SMEM_FLOATS (2 * KBUF + 2 * VBUF + 128 * PADP)
#define NKT (N_TOK / 64)

extern __shared__ float att_smem[];
__global__ __launch_bounds__(256, 2) void attn_mma_kernel() {
    float* sP = att_smem + SPO;      // [128][PADP]  Q staging / P / O staging

    const int t    = threadIdx.x;
    const int lane = t & 31;
    const int wid  = t >> 5;
    const int qt   = blockIdx.x;
    const int h    = blockIdx.y;
    const int b    = blockIdx.z;
    const int bh   = b * HEADS + h;
    const int n0   = qt * 128;

    const int r  = lane >> 2;
    const int cl = lane & 3;
    const int qrow = wid * 16 + r;

    // loader coords: each thread owns a 16-float chunk of one kv row (K and V)
    const int kvr = t >> 2;          // 0..63
    const int cb  = (t & 3) * 16;
    const float* Kgb = g_k + ((size_t)bh * N_TOK + kvr) * DH + cb;
    const float* Vgb = g_v + ((size_t)bh * N_TOK + kvr) * DH + cb;

    const uint32_t sbase = smem_u32(att_smem);
    const uint32_t kdst[2] = { sbase + (SK0 + kvr * PADK + cb) * 4u,
                               sbase + (SK1 + kvr * PADK + cb) * 4u };
    const uint32_t vdst[2] = { sbase + (SV0 + kvr * PADV + cb) * 4u,
                               sbase + (SV1 + kvr * PADV + cb) * 4u };

    // ---- issue tile 0 (cp.async), then stage Q while it flies ----
    {
#pragma unroll
        for (int c4 = 0; c4 < 4; c4++) {
            cp16(kdst[0] + c4 * 16, Kgb + c4 * 4);
            cp16(vdst[0] + c4 * 16, Vgb + c4 * 4);
        }
        CP_COMMIT();
    }
    {
        int row = t >> 1, cc = (t & 1) * 32;
        const float* Qg = g_q + ((size_t)bh * N_TOK + n0 + row) * DH + cc;
#pragma unroll
        for (int c = 0; c < 8; c++)
            *(float4*)&sP[row * PADP + cc + c * 4] = *(const float4*)&Qg[c * 4];
    }
    __syncthreads();

    // extract Q A-fragments (once)
    uint32_t qa[8][4];
#pragma unroll
    for (int k = 0; k < 8; k++) {
        qa[k][0] = __float_as_uint(sP[qrow * PADP + k * 8 + cl]);
        qa[k][1] = __float_as_uint(sP[(qrow + 8) * PADP + k * 8 + cl]);
        qa[k][2] = __float_as_uint(sP[qrow * PADP + k * 8 + cl + 4]);
        qa[k][3] = __float_as_uint(sP[(qrow + 8) * PADP + k * 8 + cl + 4]);
    }

    float o[8][4] = {};
    float l0 = 0.0f, l1 = 0.0f;

    for (int it = 0; it < NKT; it++) {
        const int buf = it & 1;
        CP_WAIT0();            // tile `it` landed (this thread's chunks)
        __syncthreads();       // all chunks visible; all warps done with other buffer

        // issue tile it+1 into the other buffer; overlaps with compute below
        if (it + 1 < NKT) {
            const float* Kg = Kgb + (size_t)(it + 1) * 64 * DH;
            const float* Vg = Vgb + (size_t)(it + 1) * 64 * DH;
            const int nbuf = buf ^ 1;
#pragma unroll
            for (int c4 = 0; c4 < 4; c4++) {
                cp16(kdst[nbuf] + c4 * 16, Kg + c4 * 4);
                cp16(vdst[nbuf] + c4 * 16, Vg + c4 * 4);
            }
            CP_COMMIT();
        }

        const float* sK = att_smem + (buf ? SK1 : SK0);   // [64 kv][PADK]
        const float* sV = att_smem + (buf ? SV1 : SV0);   // [64 kv][PADV]

        // ---- S = Q . K^T : per warp 16 x 64 ----
        float s[8][4];
#pragma unroll
        for (int nb = 0; nb < 8; nb++) {
            s[nb][0] = s[nb][1] = s[nb][2] = s[nb][3] = 0.0f;
#pragma unroll
            for (int kb = 0; kb < 8; kb++) {
                uint32_t b0 = __float_as_uint(sK[(nb * 8 + r) * PADK + kb * 8 + cl]);
                uint32_t b1 = __float_as_uint(sK[(nb * 8 + r) * PADK + kb * 8 + cl + 4]);
                mma_tf32(s[nb], qa[kb][0], qa[kb][1], qa[kb][2], qa[kb][3], b0, b1);
            }
        }

        // ---- p = exp(s - 10); row sums; P -> sP (tf32, own warp rows) ----
#pragma unroll
        for (int nb = 0; nb < 8; nb++) {
            float p0 = __expf(s[nb][0] - 10.0f);
            float p1 = __expf(s[nb][1] - 10.0f);
            float p2 = __expf(s[nb][2] - 10.0f);
            float p3 = __expf(s[nb][3] - 10.0f);
            l0 += p0 + p1;
            l1 += p2 + p3;
            *(float2*)&sP[qrow * PADP + nb * 8 + 2 * cl] =
                make_float2(tf32r(p0), tf32r(p1));
            *(float2*)&sP[(qrow + 8) * PADP + nb * 8 + 2 * cl] =
                make_float2(tf32r(p2), tf32r(p3));
        }
        // no sync: each warp reads back only its own 16 rows of sP

        // ---- O += P . V : per warp 16 x 64 ----
#pragma unroll
        for (int kb = 0; kb < 8; kb++) {
            uint32_t a0 = __float_as_uint(sP[qrow * PADP + kb * 8 + cl]);
            uint32_t a1 = __float_as_uint(sP[(qrow + 8) * PADP + kb * 8 + cl]);
            uint32_t a2 = __float_as_uint(sP[qrow * PADP + kb * 8 + cl + 4]);
            uint32_t a3 = __float_as_uint(sP[(qrow + 8) * PADP + kb * 8 + cl + 4]);
#pragma unroll
            for (int nb = 0; nb < 8; nb++) {
                uint32_t b0 = __float_as_uint(sV[(kb * 8 + cl) * PADV + nb * 8 + r]);
                uint32_t b1 = __float_as_uint(sV[(kb * 8 + cl + 4) * PADV + nb * 8 + r]);
                mma_tf32(o[nb], a0, a1, a2, a3, b0, b1);
            }
        }
    }

    // ---- finalize row sums (quad reduce) and normalize ----
    l0 += __shfl_xor_sync(0xffffffffu, l0, 1);
    l0 += __shfl_xor_sync(0xffffffffu, l0, 2);
    l1 += __shfl_xor_sync(0xffffffffu, l1, 1);
    l1 += __shfl_xor_sync(0xffffffffu, l1, 2);
    const float inv0 = 1.0f / l0;
    const float inv1 = 1.0f / l1;

    __syncthreads();   // all warps done with sP (P reads)
#pragma unroll
    for (int nb = 0; nb < 8; nb++) {
        *(float2*)&sP[qrow * PADP + nb * 8 + 2 * cl] =
            make_float2(o[nb][0] * inv0, o[nb][1] * inv0);
        *(float2*)&sP[(qrow + 8) * PADP + nb * 8 + 2 * cl] =
            make_float2(o[nb][2] * inv1, o[nb][3] * inv1);
    }
    __syncthreads();

    // transposed write: g_o[bh*DH + d][n0 + q]
    {
        const int d  = t >> 2;
        const int qc = (t & 3) * 32;
        float* Ob = g_o + ((size_t)bh * DH + d) * N_TOK + n0 + qc;
#pragma unroll
        for (int i = 0; i < 8; i++) {
            int q = qc + i * 4;
            float4 v4 = make_float4(sP[(q + 0) * PADP + d], sP[(q + 1) * PADP + d],
                                    sP[(q + 2) * PADP + d], sP[(q + 3) * PADP + d]);
            *(float4*)&Ob[i * 4] = v4;
        }
    }
}

// ---------------------------------------------------------------------------
// Kernel C (fp32 FFMA): output projection
// out[b,o,n] = sum_ci wout[o,ci]*g_o[b,ci,n] + bias
// ---------------------------------------------------------------------------
__global__ __launch_bounds__(256) void out_kernel(const float* __restrict__ wout,
                                                  const float* __restrict__ bias,
                                                  float* __restrict__ out) {
    const int nt = blockIdx.x;
    const int ot = blockIdx.y;
    const int b  = blockIdx.z;
    const int n0 = nt * 64;
    const int o0 = ot * 64;

    __shared__ float sG[16][64];
    __shared__ float sW[16][68];

    const int t  = threadIdx.x;
    const int ty = t >> 4;
    const int tx = t & 15;

    float acc[4][4] = {};
    const float* gb = g_o + (size_t)b * INNER * N_TOK;

    for (int c0 = 0; c0 < INNER; c0 += 16) {
        {
            int kk = t >> 4, nn = (t & 15) * 4;
            *(float4*)&sG[kk][nn] = *(const float4*)&gb[(size_t)(c0 + kk) * N_TOK + n0 + nn];
        }
        {
            int oo = t >> 2, k4 = (t & 3) * 4;
            float4 w4 = *(const float4*)&wout[(size_t)(o0 + oo) * INNER + c0 + k4];
            sW[k4 + 0][oo] = w4.x; sW[k4 + 1][oo] = w4.y;
            sW[k4 + 2][oo] = w4.z; sW[k4 + 3][oo] = w4.w;
        }
        __syncthreads();
#pragma unroll
        for (int kk = 0; kk < 16; kk++) {
            float4 a4 = *(float4*)&sW[kk][ty * 4];
            float4 b4 = *(float4*)&sG[kk][tx * 4];
            float a[4] = {a4.x, a4.y, a4.z, a4.w};
            float bb[4] = {b4.x, b4.y, b4.z, b4.w};
#pragma unroll
            for (int i = 0; i < 4; i++)
#pragma unroll
                for (int j = 0; j < 4; j++)
                    acc[i][j] += a[i] * bb[j];
        }
        __syncthreads();
    }

    float* ob = out + ((size_t)b * CC + o0) * N_TOK;
#pragma unroll
    for (int i = 0; i < 4; i++) {
        float bi = bias[o0 + ty * 4 + i];
        float4 v4 = make_float4(acc[i][0] + bi, acc[i][1] + bi,
                                acc[i][2] + bi, acc[i][3] + bi);
        *(float4*)&ob[(size_t)(ty * 4 + i) * N_TOK + n0 + tx * 4] = v4;
    }
}

// ---------------------------------------------------------------------------
extern "C" void kernel_launch(void* const* d_in, const int* in_sizes, int n_in,
                              void* d_out, int out_size) {
    const float* x    = (const float*)d_in[0];
    const float* wqkv = (const float*)d_in[1];
    const float* wout = (const float*)d_in[2];
    const float* bout = (const float*)d_in[3];
    float* out = (float*)d_out;

    (void)in_sizes; (void)n_in; (void)out_size;

    cudaFuncSetAttribute(attn_mma_kernel, cudaFuncAttributeMaxDynamicSharedMemorySize,
                         ATT_SMEM_FLOATS * sizeof(float));

    qkv_kernel<<<dim3(36, 24, 4), 256>>>(x, wqkv);
    attn_mma_kernel<<<dim3(18, 8, 4), 256, ATT_SMEM_FLOATS * sizeof(float)>>>();
    out_kernel<<<dim3(36, 4, 4), 256>>>(wout, bout, out);
}

// round 13
// speedup vs baseline: 1.8440x; 1.4870x over previous
#include <cuda_runtime.h>
#include <cuda_fp16.h>
#include <math.h>
#include <stdint.h>

#define N_TOK 2304
#define CC    256
#define HEADS 8
#define DH    64
#define INNER 512
#define BATCH 4

// Scratch (device globals; no runtime allocation allowed)
__device__ __half g_qh[(size_t)BATCH*HEADS*N_TOK*DH]; // [b][h][n][d]  l2norm'd * 10
__device__ __half g_kh[(size_t)BATCH*HEADS*N_TOK*DH]; // [b][h][n][d]  l2norm'd
__device__ __half g_vT[(size_t)BATCH*HEADS*DH*N_TOK]; // [b][h][d][n]  (V transposed)
__device__ float  g_o [(size_t)BATCH*INNER*N_TOK];    // [b][ci][n]

__device__ __forceinline__ uint32_t smem_u32(const void* p) {
    uint32_t a;
    asm("{ .reg .u64 t; cvta.to.shared.u64 t, %1; cvt.u32.u64 %0, t; }" : "=r"(a) : "l"(p));
    return a;
}
__device__ __forceinline__ void cp16(uint32_t dst, const void* src) {
    asm volatile("cp.async.cg.shared.global [%0], [%1], 16;" :: "r"(dst), "l"(src) : "memory");
}
#define CP_COMMIT() asm volatile("cp.async.commit_group;" ::: "memory")
#define CP_WAIT0()  asm volatile("cp.async.wait_group 0;" ::: "memory")

__device__ __forceinline__ uint32_t pack_h2(float a, float b) {
    __half2 h = __floats2half2_rn(a, b);
    return *(uint32_t*)&h;
}

// Warp-level fp16 MMA: D(16x8,f32) += A(16x16,f16) * B(16x8,f16), row.col
__device__ __forceinline__ void mma_f16(float c[4],
                                        uint32_t a0, uint32_t a1, uint32_t a2, uint32_t a3,
                                        uint32_t b0, uint32_t b1) {
    asm volatile(
        "mma.sync.aligned.m16n8k16.row.col.f32.f16.f16.f32 "
        "{%0,%1,%2,%3}, {%4,%5,%6,%7}, {%8,%9}, {%0,%1,%2,%3};"
        : "+f"(c[0]), "+f"(c[1]), "+f"(c[2]), "+f"(c[3])
        : "r"(a0), "r"(a1), "r"(a2), "r"(a3), "r"(b0), "r"(b1));
}

// ---------------------------------------------------------------------------
// Kernel A (fp32 FFMA, at roofline): QKV projection GEMM with fused l2norm
// (+SCALE on Q). fp16 rounding ONLY at the final store.
// Q,K -> half [b][h][n][d]; V -> half [b][h][d][n] (transposed via smem).
// ---------------------------------------------------------------------------
__global__ __launch_bounds__(256) void qkv_kernel(const float* __restrict__ x,
                                                  const float* __restrict__ wqkv) {
    const int nt = blockIdx.x;
    const int ot = blockIdx.y;
    const int b  = blockIdx.z;
    const int n0 = nt * 64;
    const int o0 = ot * 64;
    const int p  = ot >> 3;
    const int h  = ot & 7;

    __shared__ float sX[16][64];
    __shared__ float sW[16][68];
    __shared__ float sT[64][65];   // V transpose staging [d][n_local]

    const int t  = threadIdx.x;
    const int ty = t >> 4;   // n sub-index
    const int tx = t & 15;   // d sub-index

    float acc[4][4] = {};
    const float* xb = x + (size_t)b * CC * N_TOK;

    for (int c0 = 0; c0 < CC; c0 += 16) {
        {
            int kk = t >> 4, nn = (t & 15) * 4;
            *(float4*)&sX[kk][nn] = *(const float4*)&xb[(size_t)(c0 + kk) * N_TOK + n0 + nn];
        }
        {
            int oo = t >> 2, k4 = (t & 3) * 4;
            float4 w4 = *(const float4*)&wqkv[(size_t)(o0 + oo) * CC + c0 + k4];
            sW[k4 + 0][oo] = w4.x; sW[k4 + 1][oo] = w4.y;
            sW[k4 + 2][oo] = w4.z; sW[k4 + 3][oo] = w4.w;
        }
        __syncthreads();
#pragma unroll
        for (int kk = 0; kk < 16; kk++) {
            float4 a4 = *(float4*)&sX[kk][ty * 4];
            float4 b4 = *(float4*)&sW[kk][tx * 4];
            float a[4] = {a4.x, a4.y, a4.z, a4.w};
            float bb[4] = {b4.x, b4.y, b4.z, b4.w};
#pragma unroll
            for (int i = 0; i < 4; i++)
#pragma unroll
                for (int j = 0; j < 4; j++)
                    acc[i][j] += a[i] * bb[j];
        }
        __syncthreads();
    }

    const int bh = b * HEADS + h;

    if (p == 2) {
        // V: stage transposed [d][n_local] in fp32, then coalesced half writes
#pragma unroll
        for (int i = 0; i < 4; i++)
#pragma unroll
            for (int j = 0; j < 4; j++)
                sT[tx * 4 + j][ty * 4 + i] = acc[i][j];
        __syncthreads();

        const int d  = t >> 2;
        const int c4 = (t & 3) * 16;
        __half* dst = g_vT + ((size_t)bh * DH + d) * N_TOK + n0 + c4;
#pragma unroll
        for (int k = 0; k < 8; k++) {
            uint32_t u = pack_h2(sT[d][c4 + 2 * k], sT[d][c4 + 2 * k + 1]);
            *(uint32_t*)&dst[2 * k] = u;
        }
    } else {
        // Q/K: l2-normalize rows (d spread across 16-lane tx group)
        float ssq[4];
#pragma unroll
        for (int i = 0; i < 4; i++)
            ssq[i] = acc[i][0] * acc[i][0] + acc[i][1] * acc[i][1] +
                     acc[i][2] * acc[i][2] + acc[i][3] * acc[i][3];
#pragma unroll
        for (int off = 8; off; off >>= 1)
#pragma unroll
            for (int i = 0; i < 4; i++)
                ssq[i] += __shfl_xor_sync(0xffffffffu, ssq[i], off);

        const float sf = (p == 0) ? 10.0f : 1.0f;   // fold SCALE into Q
        __half* dstb = (p == 0 ? g_qh : g_kh) + ((size_t)bh * N_TOK + n0) * DH;
#pragma unroll
        for (int i = 0; i < 4; i++) {
            float inv = sf / fmaxf(sqrtf(ssq[i]), 1e-12f);
            uint2 u;
            u.x = pack_h2(acc[i][0] * inv, acc[i][1] * inv);
            u.y = pack_h2(acc[i][2] * inv, acc[i][3] * inv);
            *(uint2*)&dstb[(size_t)(ty * 4 + i) * DH + tx * 4] = u;
        }
    }
}

// ---------------------------------------------------------------------------
// Kernel B: fp16 m16n8k16 mma flash attention, cp.async double-buffered K/V.
// CTA = 128 q rows, 8 warps x 16 rows. kv-tiles of 64, one barrier per tile.
// P converts in-register from S C-fragments to PV A-fragments (no smem P).
// Fixed softmax max SCALE=10; O accumulates in fp32 regs across all kv-tiles.
// ---------------------------------------------------------------------------
#define PADH 72                       // halfs per smem row (conflict-free frag loads)
#define KBUFB (64 * PADH * 2)         // 9216 bytes per K or VT buffer
#define SK0B  0
#define SK1B  (KBUFB)
#define SVT0B (2 * KBUFB)
#define SVT1B (3 * KBUFB)
#define SQB   (4 * KBUFB)             // Q staging: 128 * PADH halfs = 18432 B
#define ATT_SMEM_BYTES (4 * KBUFB + 128 * PADH * 2)
#define PADP 68                       // fp32 O staging pitch (overlays K/VT buffers)
#define NKT (N_TOK / 64)

extern __shared__ char att_smem[];
__global__ __launch_bounds__(256, 2) void attn_mma_kernel() {
    __half* sQ = (__half*)(att_smem + SQB);
    float*  sO = (float*)att_smem;            // overlays K/VT buffers (used post-loop)

    const int t    = threadIdx.x;
    const int lane = t & 31;
    const int wid  = t >> 5;
    const int qt   = blockIdx.x;
    const int h    = blockIdx.y;
    const int b    = blockIdx.z;
    const int bh   = b * HEADS + h;
    const int n0   = qt * 128;

    const int r  = lane >> 2;
    const int cl = lane & 3;
    const int qrow = wid * 16 + r;

    // loader coords: row kvr (kv for K, d for VT), 32-half chunk cw
    const int kvr = t >> 2;
    const int cw  = t & 3;
    const __half* Kgb = g_kh + ((size_t)bh * N_TOK + kvr) * DH + cw * 16;
    const __half* Vgb = g_vT + ((size_t)bh * DH + kvr) * N_TOK + cw * 16;

    const uint32_t sbase = smem_u32(att_smem);
    const uint32_t kdst[2] = { sbase + SK0B  + (kvr * PADH + cw * 16) * 2u,
                               sbase + SK1B  + (kvr * PADH + cw * 16) * 2u };
    const uint32_t vdst[2] = { sbase + SVT0B + (kvr * PADH + cw * 16) * 2u,
                               sbase + SVT1B + (kvr * PADH + cw * 16) * 2u };

    // ---- issue tile 0 (cp.async), then stage Q while it flies ----
    cp16(kdst[0], Kgb);      cp16(kdst[0] + 16, Kgb + 8);
    cp16(vdst[0], Vgb);      cp16(vdst[0] + 16, Vgb + 8);
    CP_COMMIT();
    {
        int row = t >> 1, cc = (t & 1) * 32;
        const uint4* src = (const uint4*)(g_qh + ((size_t)bh * N_TOK + n0 + row) * DH + cc);
        uint4* dst = (uint4*)(sQ + row * PADH + cc);
#pragma unroll
        for (int c = 0; c < 4; c++) dst[c] = src[c];
    }
    __syncthreads();

    // extract Q A-fragments once (4 k-chunks of 16)
    uint32_t qa[4][4];
#pragma unroll
    for (int kb = 0; kb < 4; kb++) {
        qa[kb][0] = *(uint32_t*)&sQ[qrow * PADH + kb * 16 + 2 * cl];
        qa[kb][1] = *(uint32_t*)&sQ[(qrow + 8) * PADH + kb * 16 + 2 * cl];
        qa[kb][2] = *(uint32_t*)&sQ[qrow * PADH + kb * 16 + 2 * cl + 8];
        qa[kb][3] = *(uint32_t*)&sQ[(qrow + 8) * PADH + kb * 16 + 2 * cl + 8];
    }

    float o[8][4] = {};
    float l0 = 0.0f, l1 = 0.0f;

    for (int it = 0; it < NKT; it++) {
        const int buf = it & 1;
        CP_WAIT0();
        __syncthreads();

        // issue tile it+1 into the other buffer (overlaps compute)
        if (it + 1 < NKT) {
            const __half* Kg = Kgb + (size_t)(it + 1) * 64 * DH;
            const __half* Vg = Vgb + (it + 1) * 64;          // VT: advance along n
            const int nb2 = buf ^ 1;
            cp16(kdst[nb2], Kg);      cp16(kdst[nb2] + 16, Kg + 8);
            cp16(vdst[nb2], Vg);      cp16(vdst[nb2] + 16, Vg + 8);
            CP_COMMIT();
        }

        const __half* sK  = (const __half*)(att_smem + (buf ? SK1B : SK0B));
        const __half* sVT = (const __half*)(att_smem + (buf ? SVT1B : SVT0B));

        // ---- S = Q . K^T : per warp 16 x 64 (8 n-blocks x 4 k-chunks) ----
        float s[8][4];
#pragma unroll
        for (int nb = 0; nb < 8; nb++) {
            s[nb][0] = s[nb][1] = s[nb][2] = s[nb][3] = 0.0f;
#pragma unroll
            for (int kb = 0; kb < 4; kb++) {
                uint32_t b0 = *(uint32_t*)&sK[(nb * 8 + r) * PADH + kb * 16 + 2 * cl];
                uint32_t b1 = *(uint32_t*)&sK[(nb * 8 + r) * PADH + kb * 16 + 2 * cl + 8];
                mma_f16(s[nb], qa[kb][0], qa[kb][1], qa[kb][2], qa[kb][3], b0, b1);
            }
        }

        // ---- p = exp(s - 10); row sums; pack P directly into A-fragments ----
        uint32_t ph[8][2];
#pragma unroll
        for (int nb = 0; nb < 8; nb++) {
            float p0 = __expf(s[nb][0] - 10.0f);
            float p1 = __expf(s[nb][1] - 10.0f);
            float p2 = __expf(s[nb][2] - 10.0f);
            float p3 = __expf(s[nb][3] - 10.0f);
            l0 += p0 + p1;
            l1 += p2 + p3;
            ph[nb][0] = pack_h2(p0, p1);   // row r,   cols 2cl,2cl+1
            ph[nb][1] = pack_h2(p2, p3);   // row r+8, cols 2cl,2cl+1
        }

        // ---- O += P . V : per warp 16 x 64; A = P from registers ----
#pragma unroll
        for (int kb = 0; kb < 4; kb++) {
            uint32_t a0 = ph[2 * kb][0];
            uint32_t a1 = ph[2 * kb][1];
            uint32_t a2 = ph[2 * kb + 1][0];
            uint32_t a3 = ph[2 * kb + 1][1];
#pragma unroll
            for (int nb = 0; nb < 8; nb++) {
                uint32_t b0 = *(uint32_t*)&sVT[(nb * 8 + r) * PADH + kb * 16 + 2 * cl];
                uint32_t b1 = *(uint32_t*)&sVT[(nb * 8 + r) * PADH + kb * 16 + 2 * cl + 8];
                mma_f16(o[nb], a0, a1, a2, a3, b0, b1);
            }
        }
    }

    // ---- finalize row sums (quad reduce) and normalize ----
    l0 += __shfl_xor_sync(0xffffffffu, l0, 1);
    l0 += __shfl_xor_sync(0xffffffffu, l0, 2);
    l1 += __shfl_xor_sync(0xffffffffu, l1, 1);
    l1 += __shfl_xor_sync(0xffffffffu, l1, 2);
    const float inv0 = 1.0f / l0;
    const float inv1 = 1.0f / l1;

    __syncthreads();   // everyone done reading K/VT buffers (sO overlays them)
#pragma unroll
    for (int nb = 0; nb < 8; nb++) {
        *(float2*)&sO[qrow * PADP + nb * 8 + 2 * cl] =
            make_float2(o[nb][0] * inv0, o[nb][1] * inv0);
        *(float2*)&sO[(qrow + 8) * PADP + nb * 8 + 2 * cl] =
            make_float2(o[nb][2] * inv1, o[nb][3] * inv1);
    }
    __syncthreads();

    // transposed write: g_o[bh*DH + d][n0 + q]
    {
        const int d  = t >> 2;
        const int qc = (t & 3) * 32;
        float* Ob = g_o + ((size_t)bh * DH + d) * N_TOK + n0 + qc;
#pragma unroll
        for (int i = 0; i < 8; i++) {
            int q = qc + i * 4;
            float4 v4 = make_float4(sO[(q + 0) * PADP + d], sO[(q + 1) * PADP + d],
                                    sO[(q + 2) * PADP + d], sO[(q + 3) * PADP + d]);
            *(float4*)&Ob[i * 4] = v4;
        }
    }
}

// ---------------------------------------------------------------------------
// Kernel C (fp32 FFMA): output projection
// out[b,o,n] = sum_ci wout[o,ci]*g_o[b,ci,n] + bias
// ---------------------------------------------------------------------------
__global__ __launch_bounds__(256) void out_kernel(const float* __restrict__ wout,
                                                  const float* __restrict__ bias,
                                                  float* __restrict__ out) {
    const int nt = blockIdx.x;
    const int ot = blockIdx.y;
    const int b  = blockIdx.z;
    const int n0 = nt * 64;
    const int o0 = ot * 64;

    __shared__ float sG[16][64];
    __shared__ float sW[16][68];

    const int t  = threadIdx.x;
    const int ty = t >> 4;
    const int tx = t & 15;

    float acc[4][4] = {};
    const float* gb = g_o + (size_t)b * INNER * N_TOK;

    for (int c0 = 0; c0 < INNER; c0 += 16) {
        {
            int kk = t >> 4, nn = (t & 15) * 4;
            *(float4*)&sG[kk][nn] = *(const float4*)&gb[(size_t)(c0 + kk) * N_TOK + n0 + nn];
        }
        {
            int oo = t >> 2, k4 = (t & 3) * 4;
            float4 w4 = *(const float4*)&wout[(size_t)(o0 + oo) * INNER + c0 + k4];
            sW[k4 + 0][oo] = w4.x; sW[k4 + 1][oo] = w4.y;
            sW[k4 + 2][oo] = w4.z; sW[k4 + 3][oo] = w4.w;
        }
        __syncthreads();
#pragma unroll
        for (int kk = 0; kk < 16; kk++) {
            float4 a4 = *(float4*)&sW[kk][ty * 4];
            float4 b4 = *(float4*)&sG[kk][tx * 4];
            float a[4] = {a4.x, a4.y, a4.z, a4.w};
            float bb[4] = {b4.x, b4.y, b4.z, b4.w};
#pragma unroll
            for (int i = 0; i < 4; i++)
#pragma unroll
                for (int j = 0; j < 4; j++)
                    acc[i][j] += a[i] * bb[j];
        }
        __syncthreads();
    }

    float* ob = out + ((size_t)b * CC + o0) * N_TOK;
#pragma unroll
    for (int i = 0; i < 4; i++) {
        float bi = bias[o0 + ty * 4 + i];
        float4 v4 = make_float4(acc[i][0] + bi, acc[i][1] + bi,
                                acc[i][2] + bi, acc[i][3] + bi);
        *(float4*)&ob[(size_t)(ty * 4 + i) * N_TOK + n0 + tx * 4] = v4;
    }
}

// ---------------------------------------------------------------------------
extern "C" void kernel_launch(void* const* d_in, const int* in_sizes, int n_in,
                              void* d_out, int out_size) {
    const float* x    = (const float*)d_in[0];
    const float* wqkv = (const float*)d_in[1];
    const float* wout = (const float*)d_in[2];
    const float* bout = (const float*)d_in[3];
    float* out = (float*)d_out;

    (void)in_sizes; (void)n_in; (void)out_size;

    cudaFuncSetAttribute(attn_mma_kernel, cudaFuncAttributeMaxDynamicSharedMemorySize,
                         ATT_SMEM_BYTES);

    qkv_kernel<<<dim3(36, 24, 4), 256>>>(x, wqkv);
    attn_mma_kernel<<<dim3(18, 8, 4), 256, ATT_SMEM_BYTES>>>();
    out_kernel<<<dim3(36, 4, 4), 256>>>(wout, bout, out);
}

// round 14
// speedup vs baseline: 2.6434x; 1.4335x over previous
#include <cuda_runtime.h>
#include <cuda_fp16.h>
#include <math.h>
#include <stdint.h>

#define N_TOK 2304
#define CC    256
#define HEADS 8
#define DH    64
#define INNER 512
#define BATCH 4

// Scratch (device globals; no runtime allocation allowed)
__device__ __half g_xh[(size_t)BATCH*N_TOK*CC];       // xT hi  [b][n][c]
__device__ __half g_xl[(size_t)BATCH*N_TOK*CC];       // xT lo
__device__ __half g_wh[(size_t)3*INNER*CC];           // wqkv hi [o][c]
__device__ __half g_wl[(size_t)3*INNER*CC];           // wqkv lo
__device__ __half g_woh[(size_t)CC*INNER];            // wout hi [o][ci]
__device__ __half g_wol[(size_t)CC*INNER];            // wout lo
__device__ __half g_qh[(size_t)BATCH*HEADS*N_TOK*DH]; // [b][h][n][d]  l2norm'd * 10
__device__ __half g_kh[(size_t)BATCH*HEADS*N_TOK*DH]; // [b][h][n][d]  l2norm'd
__device__ __half g_vT[(size_t)BATCH*HEADS*DH*N_TOK]; // [b][h][d][n]  (V transposed)
__device__ __half g_ah[(size_t)BATCH*N_TOK*INNER];    // attention out hi [b][n][ci]
__device__ __half g_al[(size_t)BATCH*N_TOK*INNER];    // attention out lo

__device__ __forceinline__ uint32_t smem_u32(const void* p) {
    uint32_t a;
    asm("{ .reg .u64 t; cvta.to.shared.u64 t, %1; cvt.u32.u64 %0, t; }" : "=r"(a) : "l"(p));
    return a;
}
__device__ __forceinline__ void cp16(uint32_t dst, const void* src) {
    asm volatile("cp.async.cg.shared.global [%0], [%1], 16;" :: "r"(dst), "l"(src) : "memory");
}
#define CP_COMMIT() asm volatile("cp.async.commit_group;" ::: "memory")
#define CP_WAIT0()  asm volatile("cp.async.wait_group 0;" ::: "memory")

__device__ __forceinline__ uint32_t pack_h2(float a, float b) {
    __half2 h = __floats2half2_rn(a, b);
    return *(uint32_t*)&h;
}
__device__ __forceinline__ uint32_t pack2h(__half a, __half b) {
    __half2 h = __halves2half2(a, b);
    return *(uint32_t*)&h;
}

// Warp-level fp16 MMA: D(16x8,f32) += A(16x16,f16) * B(16x8,f16), row.col
__device__ __forceinline__ void mma_f16(float c[4],
                                        uint32_t a0, uint32_t a1, uint32_t a2, uint32_t a3,
                                        uint32_t b0, uint32_t b1) {
    asm volatile(
        "mma.sync.aligned.m16n8k16.row.col.f32.f16.f16.f32 "
        "{%0,%1,%2,%3}, {%4,%5,%6,%7}, {%8,%9}, {%0,%1,%2,%3};"
        : "+f"(c[0]), "+f"(c[1]), "+f"(c[2]), "+f"(c[3])
        : "r"(a0), "r"(a1), "r"(a2), "r"(a3), "r"(b0), "r"(b1));
}

// ---------------------------------------------------------------------------
// Kernel 0a: split weights to hi/lo fp16
// ---------------------------------------------------------------------------
__global__ __launch_bounds__(256) void convert_w_kernel(const float* __restrict__ wqkv,
                                                        const float* __restrict__ wout) {
    int i = blockIdx.x * 256 + threadIdx.x;
    const int NW = 3 * INNER * CC;
    if (i < NW) {
        float v = wqkv[i];
        __half h = __float2half_rn(v);
        g_wh[i] = h;
        g_wl[i] = __float2half_rn(v - __half2float(h));
    } else {
        int j = i - NW;
        if (j < CC * INNER) {
            float v = wout[j];
            __half h = __float2half_rn(v);
            g_woh[j] = h;
            g_wol[j] = __float2half_rn(v - __half2float(h));
        }
    }
}

// ---------------------------------------------------------------------------
// Kernel 0b: transpose + split x: [b][c][n] fp32 -> [b][n][c] hi/lo fp16
// ---------------------------------------------------------------------------
__global__ __launch_bounds__(256) void convert_x_kernel(const float* __restrict__ x) {
    __shared__ float sm[32][33];
    const int nt = blockIdx.x, ct = blockIdx.y, b = blockIdx.z;
    const int tx = threadIdx.x & 31, ty = threadIdx.x >> 5;

    const float* xb = x + ((size_t)b * CC + ct * 32) * N_TOK + nt * 32;
#pragma unroll
    for (int k = 0; k < 4; k++)
        sm[ty + k * 8][tx] = xb[(size_t)(ty + k * 8) * N_TOK + tx];
    __syncthreads();

#pragma unroll
    for (int k = 0; k < 4; k++) {
        int nl = ty + k * 8;
        float v = sm[tx][nl];
        __half h = __float2half_rn(v);
        size_t idx = ((size_t)b * N_TOK + nt * 32 + nl) * CC + ct * 32 + tx;
        g_xh[idx] = h;
        g_xl[idx] = __float2half_rn(v - __half2float(h));
    }
}

// ---------------------------------------------------------------------------
// Kernel A: QKV projection via split-fp16 mma (3-term, fp32-quality).
// C[n][o] = xT[n][c] . W[o][c]^T. CTA: 128 tokens x 64 o (one (part,head)).
// 8 warps = 2(n-half? no: 8 x 16 token-rows). Fused l2norm per token row.
// ---------------------------------------------------------------------------
#define QPADC 72
#define QSXH 0
#define QSXL (128 * QPADC * 2)
#define QSWH (2 * 128 * QPADC * 2)
#define QSWL (QSWH + 64 * QPADC * 2)
#define QSMEM_BYTES (QSWL + 64 * QPADC * 2)   // 55296
#define PADT 136

extern __shared__ char qkv_smem[];
__global__ __launch_bounds__(256, 2) void qkv_mma_kernel() {
    __half* sXh = (__half*)(qkv_smem + QSXH);
    __half* sXl = (__half*)(qkv_smem + QSXL);
    __half* sWh = (__half*)(qkv_smem + QSWH);
    __half* sWl = (__half*)(qkv_smem + QSWL);

    const int nt = blockIdx.x;      // 0..17
    const int oy = blockIdx.y;      // 0..23
    const int b  = blockIdx.z;
    const int n0 = nt * 128;
    const int o0 = oy * 64;
    const int p  = oy >> 3;
    const int h  = oy & 7;

    const int t    = threadIdx.x;
    const int lane = t & 31;
    const int wid  = t >> 5;
    const int r    = lane >> 2;
    const int cl   = lane & 3;
    const int qrow = wid * 16 + r;

    // loaders
    const int xrow = t >> 1, xseg = (t & 1) * 32;
    const int wrow = t >> 2, wseg = (t & 3) * 16;
    const __half* Xh = g_xh + ((size_t)b * N_TOK + n0 + xrow) * CC + xseg;
    const __half* Xl = g_xl + ((size_t)b * N_TOK + n0 + xrow) * CC + xseg;
    const __half* Wh = g_wh + (size_t)(o0 + wrow) * CC + wseg;
    const __half* Wl = g_wl + (size_t)(o0 + wrow) * CC + wseg;

    const uint32_t sbase = smem_u32(qkv_smem);
    const uint32_t xdh = sbase + QSXH + (xrow * QPADC + xseg) * 2;
    const uint32_t xdl = sbase + QSXL + (xrow * QPADC + xseg) * 2;
    const uint32_t wdh = sbase + QSWH + (wrow * QPADC + wseg) * 2;
    const uint32_t wdl = sbase + QSWL + (wrow * QPADC + wseg) * 2;

    float acc[8][4] = {};

    for (int c0 = 0; c0 < CC; c0 += 64) {
        __syncthreads();
#pragma unroll
        for (int k = 0; k < 4; k++) {
            cp16(xdh + k * 16, Xh + c0 + k * 8);
            cp16(xdl + k * 16, Xl + c0 + k * 8);
        }
        cp16(wdh, Wh + c0);      cp16(wdh + 16, Wh + c0 + 8);
        cp16(wdl, Wl + c0);      cp16(wdl + 16, Wl + c0 + 8);
        CP_COMMIT();
        CP_WAIT0();
        __syncthreads();

#pragma unroll
        for (int kc = 0; kc < 4; kc++) {
            uint32_t ah[4], al[4];
            ah[0] = *(uint32_t*)&sXh[qrow * QPADC + kc * 16 + 2 * cl];
            ah[1] = *(uint32_t*)&sXh[(qrow + 8) * QPADC + kc * 16 + 2 * cl];
            ah[2] = *(uint32_t*)&sXh[qrow * QPADC + kc * 16 + 2 * cl + 8];
            ah[3] = *(uint32_t*)&sXh[(qrow + 8) * QPADC + kc * 16 + 2 * cl + 8];
            al[0] = *(uint32_t*)&sXl[qrow * QPADC + kc * 16 + 2 * cl];
            al[1] = *(uint32_t*)&sXl[(qrow + 8) * QPADC + kc * 16 + 2 * cl];
            al[2] = *(uint32_t*)&sXl[qrow * QPADC + kc * 16 + 2 * cl + 8];
            al[3] = *(uint32_t*)&sXl[(qrow + 8) * QPADC + kc * 16 + 2 * cl + 8];
#pragma unroll
            for (int ob = 0; ob < 8; ob++) {
                uint32_t bh0 = *(uint32_t*)&sWh[(ob * 8 + r) * QPADC + kc * 16 + 2 * cl];
                uint32_t bh1 = *(uint32_t*)&sWh[(ob * 8 + r) * QPADC + kc * 16 + 2 * cl + 8];
                uint32_t bl0 = *(uint32_t*)&sWl[(ob * 8 + r) * QPADC + kc * 16 + 2 * cl];
                uint32_t bl1 = *(uint32_t*)&sWl[(ob * 8 + r) * QPADC + kc * 16 + 2 * cl + 8];
                mma_f16(acc[ob], ah[0], ah[1], ah[2], ah[3], bh0, bh1);
                mma_f16(acc[ob], ah[0], ah[1], ah[2], ah[3], bl0, bl1);
                mma_f16(acc[ob], al[0], al[1], al[2], al[3], bh0, bh1);
            }
        }
    }

    const int bh = b * HEADS + h;

    if (p == 2) {
        // V: transpose via smem (half) then coalesced writes to g_vT [d][n]
        __half* sVt = (__half*)qkv_smem;   // [64][PADT]
        __syncthreads();
#pragma unroll
        for (int ob = 0; ob < 8; ob++) {
            int d = ob * 8 + 2 * cl;
            sVt[d * PADT + qrow]           = __float2half_rn(acc[ob][0]);
            sVt[(d + 1) * PADT + qrow]     = __float2half_rn(acc[ob][1]);
            sVt[d * PADT + qrow + 8]       = __float2half_rn(acc[ob][2]);
            sVt[(d + 1) * PADT + qrow + 8] = __float2half_rn(acc[ob][3]);
        }
        __syncthreads();
        const int d = t >> 2, seg = (t & 3) * 32;
        const uint4* src = (const uint4*)&sVt[d * PADT + seg];
        __half* dst = g_vT + ((size_t)bh * DH + d) * N_TOK + n0 + seg;
#pragma unroll
        for (int k = 0; k < 4; k++)
            *(uint4*)&dst[k * 8] = src[k];
    } else {
        // l2norm per token row (in-thread over 8 ob + quad shuffle)
        float l0 = 0.0f, l1 = 0.0f;
#pragma unroll
        for (int ob = 0; ob < 8; ob++) {
            l0 += acc[ob][0] * acc[ob][0] + acc[ob][1] * acc[ob][1];
            l1 += acc[ob][2] * acc[ob][2] + acc[ob][3] * acc[ob][3];
        }
        l0 += __shfl_xor_sync(0xffffffffu, l0, 1);
        l0 += __shfl_xor_sync(0xffffffffu, l0, 2);
        l1 += __shfl_xor_sync(0xffffffffu, l1, 1);
        l1 += __shfl_xor_sync(0xffffffffu, l1, 2);
        const float sf = (p == 0) ? 10.0f : 1.0f;
        const float inv0 = sf / fmaxf(sqrtf(l0), 1e-12f);
        const float inv1 = sf / fmaxf(sqrtf(l1), 1e-12f);

        __half* dstb = (p == 0 ? g_qh : g_kh) + ((size_t)bh * N_TOK + n0) * DH;
#pragma unroll
        for (int ob = 0; ob < 8; ob++) {
            *(uint32_t*)&dstb[(size_t)qrow * DH + ob * 8 + 2 * cl] =
                pack_h2(acc[ob][0] * inv0, acc[ob][1] * inv0);
            *(uint32_t*)&dstb[(size_t)(qrow + 8) * DH + ob * 8 + 2 * cl] =
                pack_h2(acc[ob][2] * inv1, acc[ob][3] * inv1);
        }
    }
}

// ---------------------------------------------------------------------------
// Kernel B: fp16 m16n8k16 mma flash attention, cp.async double-buffered K/V.
// Epilogue writes O as hi/lo fp16 [b][n][ci] for the split-mma out projection.
// ---------------------------------------------------------------------------
#define PADH 72
#define KBUFB (64 * PADH * 2)
#define SK0B  0
#define SK1B  (KBUFB)
#define SVT0B (2 * KBUFB)
#define SVT1B (3 * KBUFB)
#define SQB   (4 * KBUFB)
#define ATT_SMEM_BYTES (4 * KBUFB + 128 * PADH * 2)
#define PADP 68
#define NKT (N_TOK / 64)

extern __shared__ char att_smem[];
__global__ __launch_bounds__(256, 2) void attn_mma_kernel() {
    __half* sQ = (__half*)(att_smem + SQB);
    float*  sO = (float*)att_smem;            // overlays K/VT buffers (post-loop)

    const int t    = threadIdx.x;
    const int lane = t & 31;
    const int wid  = t >> 5;
    const int qt   = blockIdx.x;
    const int h    = blockIdx.y;
    const int b    = blockIdx.z;
    const int bh   = b * HEADS + h;
    const int n0   = qt * 128;

    const int r  = lane >> 2;
    const int cl = lane & 3;
    const int qrow = wid * 16 + r;

    const int kvr = t >> 2;
    const int cw  = t & 3;
    const __half* Kgb = g_kh + ((size_t)bh * N_TOK + kvr) * DH + cw * 16;
    const __half* Vgb = g_vT + ((size_t)bh * DH + kvr) * N_TOK + cw * 16;

    const uint32_t sbase = smem_u32(att_smem);
    const uint32_t kdst[2] = { sbase + SK0B  + (kvr * PADH + cw * 16) * 2u,
                               sbase + SK1B  + (kvr * PADH + cw * 16) * 2u };
    const uint32_t vdst[2] = { sbase + SVT0B + (kvr * PADH + cw * 16) * 2u,
                               sbase + SVT1B + (kvr * PADH + cw * 16) * 2u };

    cp16(kdst[0], Kgb);      cp16(kdst[0] + 16, Kgb + 8);
    cp16(vdst[0], Vgb);      cp16(vdst[0] + 16, Vgb + 8);
    CP_COMMIT();
    {
        int row = t >> 1, cc = (t & 1) * 32;
        const uint4* src = (const uint4*)(g_qh + ((size_t)bh * N_TOK + n0 + row) * DH + cc);
        uint4* dst = (uint4*)(sQ + row * PADH + cc);
#pragma unroll
        for (int c = 0; c < 4; c++) dst[c] = src[c];
    }
    __syncthreads();

    uint32_t qa[4][4];
#pragma unroll
    for (int kb = 0; kb < 4; kb++) {
        qa[kb][0] = *(uint32_t*)&sQ[qrow * PADH + kb * 16 + 2 * cl];
        qa[kb][1] = *(uint32_t*)&sQ[(qrow + 8) * PADH + kb * 16 + 2 * cl];
        qa[kb][2] = *(uint32_t*)&sQ[qrow * PADH + kb * 16 + 2 * cl + 8];
        qa[kb][3] = *(uint32_t*)&sQ[(qrow + 8) * PADH + kb * 16 + 2 * cl + 8];
    }

    float o[8][4] = {};
    float l0 = 0.0f, l1 = 0.0f;

    for (int it = 0; it < NKT; it++) {
        const int buf = it & 1;
        CP_WAIT0();
        __syncthreads();

        if (it + 1 < NKT) {
            const __half* Kg = Kgb + (size_t)(it + 1) * 64 * DH;
            const __half* Vg = Vgb + (it + 1) * 64;
            const int nb2 = buf ^ 1;
            cp16(kdst[nb2], Kg);      cp16(kdst[nb2] + 16, Kg + 8);
            cp16(vdst[nb2], Vg);      cp16(vdst[nb2] + 16, Vg + 8);
            CP_COMMIT();
        }

        const __half* sK  = (const __half*)(att_smem + (buf ? SK1B : SK0B));
        const __half* sVT = (const __half*)(att_smem + (buf ? SVT1B : SVT0B));

        float s[8][4];
#pragma unroll
        for (int nb = 0; nb < 8; nb++) {
            s[nb][0] = s[nb][1] = s[nb][2] = s[nb][3] = 0.0f;
#pragma unroll
            for (int kb = 0; kb < 4; kb++) {
                uint32_t b0 = *(uint32_t*)&sK[(nb * 8 + r) * PADH + kb * 16 + 2 * cl];
                uint32_t b1 = *(uint32_t*)&sK[(nb * 8 + r) * PADH + kb * 16 + 2 * cl + 8];
                mma_f16(s[nb], qa[kb][0], qa[kb][1], qa[kb][2], qa[kb][3], b0, b1);
            }
        }

        uint32_t ph[8][2];
#pragma unroll
        for (int nb = 0; nb < 8; nb++) {
            float p0 = __expf(s[nb][0] - 10.0f);
            float p1 = __expf(s[nb][1] - 10.0f);
            float p2 = __expf(s[nb][2] - 10.0f);
            float p3 = __expf(s[nb][3] - 10.0f);
            l0 += p0 + p1;
            l1 += p2 + p3;
            ph[nb][0] = pack_h2(p0, p1);
            ph[nb][1] = pack_h2(p2, p3);
        }

#pragma unroll
        for (int kb = 0; kb < 4; kb++) {
            uint32_t a0 = ph[2 * kb][0];
            uint32_t a1 = ph[2 * kb][1];
            uint32_t a2 = ph[2 * kb + 1][0];
            uint32_t a3 = ph[2 * kb + 1][1];
#pragma unroll
            for (int nb = 0; nb < 8; nb++) {
                uint32_t b0 = *(uint32_t*)&sVT[(nb * 8 + r) * PADH + kb * 16 + 2 * cl];
                uint32_t b1 = *(uint32_t*)&sVT[(nb * 8 + r) * PADH + kb * 16 + 2 * cl + 8];
                mma_f16(o[nb], a0, a1, a2, a3, b0, b1);
            }
        }
    }

    l0 += __shfl_xor_sync(0xffffffffu, l0, 1);
    l0 += __shfl_xor_sync(0xffffffffu, l0, 2);
    l1 += __shfl_xor_sync(0xffffffffu, l1, 1);
    l1 += __shfl_xor_sync(0xffffffffu, l1, 2);
    const float inv0 = 1.0f / l0;
    const float inv1 = 1.0f / l1;

    __syncthreads();   // done reading K/VT buffers (sO overlays them)
#pragma unroll
    for (int nb = 0; nb < 8; nb++) {
        *(float2*)&sO[qrow * PADP + nb * 8 + 2 * cl] =
            make_float2(o[nb][0] * inv0, o[nb][1] * inv0);
        *(float2*)&sO[(qrow + 8) * PADP + nb * 8 + 2 * cl] =
            make_float2(o[nb][2] * inv1, o[nb][3] * inv1);
    }
    __syncthreads();

    // write O as hi/lo halves: g_ah/g_al [b][n0+row][h*64 + d]
    {
        const int row = t >> 1;
        const int seg = (t & 1) * 32;
        const float* src = sO + row * PADP + seg;
        const size_t base = ((size_t)b * N_TOK + n0 + row) * INNER + h * DH + seg;
#pragma unroll
        for (int c4 = 0; c4 < 4; c4++) {
            uint32_t uh[4], ul[4];
#pragma unroll
            for (int j = 0; j < 4; j++) {
                float v0 = src[c4 * 8 + 2 * j];
                float v1 = src[c4 * 8 + 2 * j + 1];
                __half h0 = __float2half_rn(v0);
                __half h1 = __float2half_rn(v1);
                uh[j] = pack2h(h0, h1);
                ul[j] = pack_h2(v0 - __half2float(h0), v1 - __half2float(h1));
            }
            *(uint4*)&g_ah[base + c4 * 8] = make_uint4(uh[0], uh[1], uh[2], uh[3]);
            *(uint4*)&g_al[base + c4 * 8] = make_uint4(ul[0], ul[1], ul[2], ul[3]);
        }
    }
}

// ---------------------------------------------------------------------------
// Kernel C: output projection via split-fp16 mma (3-term).
// out[o][n] = wout[o][ci] . G[n][ci]^T + bias. CTA: 64 o x 128 n, K=512.
// ---------------------------------------------------------------------------
#define OSGH 0
#define OSGL (128 * QPADC * 2)
#define OSWH (2 * 128 * QPADC * 2)
#define OSWL (OSWH + 64 * QPADC * 2)
#define OSMEM_BYTES (OSWL + 64 * QPADC * 2)   // 55296

extern __shared__ char out_smem[];
__global__ __launch_bounds__(256, 2) void out_mma_kernel(const float* __restrict__ bias,
                                                         float* __restrict__ out) {
    __half* sGh = (__half*)(out_smem + OSGH);
    __half* sGl = (__half*)(out_smem + OSGL);
    __half* sWh = (__half*)(out_smem + OSWH);
    __half* sWl = (__half*)(out_smem + OSWL);

    const int nt = blockIdx.x;   // 0..17
    const int ot = blockIdx.y;   // 0..3
    const int b  = blockIdx.z;
    const int n0 = nt * 128;
    const int o0 = ot * 64;

    const int t    = threadIdx.x;
    const int lane = t & 31;
    const int wid  = t >> 5;
    const int wo   = wid & 3;
    const int wn   = wid >> 2;
    const int r    = lane >> 2;
    const int cl   = lane & 3;
    const int orow = wo * 16 + r;

    const int grow = t >> 1, gseg = (t & 1) * 32;
    const int wrow = t >> 2, wseg = (t & 3) * 16;
    const __half* Gh = g_ah + ((size_t)b * N_TOK + n0 + grow) * INNER + gseg;
    const __half* Gl = g_al + ((size_t)b * N_TOK + n0 + grow) * INNER + gseg;
    const __half* Wh = g_woh + (size_t)(o0 + wrow) * INNER + wseg;
    const __half* Wl = g_wol + (size_t)(o0 + wrow) * INNER + wseg;

    const uint32_t sbase = smem_u32(out_smem);
    const uint32_t gdh = sbase + OSGH + (grow * QPADC + gseg) * 2;
    const uint32_t gdl = sbase + OSGL + (grow * QPADC + gseg) * 2;
    const uint32_t wdh = sbase + OSWH + (wrow * QPADC + wseg) * 2;
    const uint32_t wdl = sbase + OSWL + (wrow * QPADC + wseg) * 2;

    float acc[8][4] = {};

    for (int c0 = 0; c0 < INNER; c0 += 64) {
        __syncthreads();
#pragma unroll
        for (int k = 0; k < 4; k++) {
            cp16(gdh + k * 16, Gh + c0 + k * 8);
            cp16(gdl + k * 16, Gl + c0 + k * 8);
        }
        cp16(wdh, Wh + c0);      cp16(wdh + 16, Wh + c0 + 8);
        cp16(wdl, Wl + c0);      cp16(wdl + 16, Wl + c0 + 8);
        CP_COMMIT();
        CP_WAIT0();
        __syncthreads();

#pragma unroll
        for (int kc = 0; kc < 4; kc++) {
            uint32_t ah[4], al[4];
            ah[0] = *(uint32_t*)&sWh[orow * QPADC + kc * 16 + 2 * cl];
            ah[1] = *(uint32_t*)&sWh[(orow + 8) * QPADC + kc * 16 + 2 * cl];
            ah[2] = *(uint32_t*)&sWh[orow * QPADC + kc * 16 + 2 * cl + 8];
            ah[3] = *(uint32_t*)&sWh[(orow + 8) * QPADC + kc * 16 + 2 * cl + 8];
            al[0] = *(uint32_t*)&sWl[orow * QPADC + kc * 16 + 2 * cl];
            al[1] = *(uint32_t*)&sWl[(orow + 8) * QPADC + kc * 16 + 2 * cl];
            al[2] = *(uint32_t*)&sWl[orow * QPADC + kc * 16 + 2 * cl + 8];
            al[3] = *(uint32_t*)&sWl[(orow + 8) * QPADC + kc * 16 + 2 * cl + 8];
#pragma unroll
            for (int nb = 0; nb < 8; nb++) {
                int gn = wn * 64 + nb * 8 + r;
                uint32_t bh0 = *(uint32_t*)&sGh[gn * QPADC + kc * 16 + 2 * cl];
                uint32_t bh1 = *(uint32_t*)&sGh[gn * QPADC + kc * 16 + 2 * cl + 8];
                uint32_t bl0 = *(uint32_t*)&sGl[gn * QPADC + kc * 16 + 2 * cl];
                uint32_t bl1 = *(uint32_t*)&sGl[gn * QPADC + kc * 16 + 2 * cl + 8];
                mma_f16(acc[nb], ah[0], ah[1], ah[2], ah[3], bh0, bh1);
                mma_f16(acc[nb], ah[0], ah[1], ah[2], ah[3], bl0, bl1);
                mma_f16(acc[nb], al[0], al[1], al[2], al[3], bh0, bh1);
            }
        }
    }

    const int o_g = o0 + orow;
    const float bi0 = bias[o_g];
    const float bi1 = bias[o_g + 8];
    float* ob0 = out + ((size_t)b * CC + o_g) * N_TOK + n0 + wn * 64;
    float* ob1 = ob0 + 8 * N_TOK;
#pragma unroll
    for (int nb = 0; nb < 8; nb++) {
        *(float2*)&ob0[nb * 8 + 2 * cl] = make_float2(acc[nb][0] + bi0, acc[nb][1] + bi0);
        *(float2*)&ob1[nb * 8 + 2 * cl] = make_float2(acc[nb][2] + bi1, acc[nb][3] + bi1);
    }
}

// ---------------------------------------------------------------------------
extern "C" void kernel_launch(void* const* d_in, const int* in_sizes, int n_in,
                              void* d_out, int out_size) {
    const float* x    = (const float*)d_in[0];
    const float* wqkv = (const float*)d_in[1];
    const float* wout = (const float*)d_in[2];
    const float* bout = (const float*)d_in[3];
    float* out = (float*)d_out;

    (void)in_sizes; (void)n_in; (void)out_size;

    cudaFuncSetAttribute(qkv_mma_kernel, cudaFuncAttributeMaxDynamicSharedMemorySize,
                         QSMEM_BYTES);
    cudaFuncSetAttribute(attn_mma_kernel, cudaFuncAttributeMaxDynamicSharedMemorySize,
                         ATT_SMEM_BYTES);
    cudaFuncSetAttribute(out_mma_kernel, cudaFuncAttributeMaxDynamicSharedMemorySize,
                         OSMEM_BYTES);

    convert_w_kernel<<<(3 * INNER * CC + CC * INNER) / 256, 256>>>(wqkv, wout);
    convert_x_kernel<<<dim3(N_TOK / 32, CC / 32, BATCH), 256>>>(x);
    qkv_mma_kernel<<<dim3(18, 24, 4), 256, QSMEM_BYTES>>>();
    attn_mma_kernel<<<dim3(18, 8, 4), 256, ATT_SMEM_BYTES>>>();
    out_mma_kernel<<<dim3(18, 4, 4), 256, OSMEM_BYTES>>>(bout, out);
}

// round 15
// speedup vs baseline: 2.7942x; 1.0571x over previous
#include <cuda_runtime.h>
#include <cuda_fp16.h>
#include <math.h>
#include <stdint.h>

#define N_TOK 2304
#define CC    256
#define HEADS 8
#define DH    64
#define INNER 512
#define BATCH 4

#define QSCALE 14.4269504088896341f   // 10 * log2(e)

// Scratch (device globals; no runtime allocation allowed)
__device__ __half g_xh[(size_t)BATCH*N_TOK*CC];       // xT hi  [b][n][c]
__device__ __half g_xl[(size_t)BATCH*N_TOK*CC];       // xT lo
__device__ __half g_wh[(size_t)3*INNER*CC];           // wqkv hi [o][c]
__device__ __half g_wl[(size_t)3*INNER*CC];           // wqkv lo
__device__ __half g_woh[(size_t)CC*INNER];            // wout hi [o][ci]
__device__ __half g_wol[(size_t)CC*INNER];            // wout lo
__device__ __half g_qh[(size_t)BATCH*HEADS*N_TOK*DH]; // [b][h][n][d]  l2norm'd * 10*log2e
__device__ __half g_kh[(size_t)BATCH*HEADS*N_TOK*DH]; // [b][h][n][d]  l2norm'd
__device__ __half g_vT[(size_t)BATCH*HEADS*DH*N_TOK]; // [b][h][d][n]  (V transposed)
__device__ __half g_ah[(size_t)BATCH*N_TOK*INNER];    // attention out hi [b][n][ci]
__device__ __half g_al[(size_t)BATCH*N_TOK*INNER];    // attention out lo

__device__ __forceinline__ uint32_t smem_u32(const void* p) {
    uint32_t a;
    asm("{ .reg .u64 t; cvta.to.shared.u64 t, %1; cvt.u32.u64 %0, t; }" : "=r"(a) : "l"(p));
    return a;
}
__device__ __forceinline__ void cp16(uint32_t dst, const void* src) {
    asm volatile("cp.async.cg.shared.global [%0], [%1], 16;" :: "r"(dst), "l"(src) : "memory");
}
#define CP_COMMIT() asm volatile("cp.async.commit_group;" ::: "memory")
#define CP_WAIT0()  asm volatile("cp.async.wait_group 0;" ::: "memory")

__device__ __forceinline__ uint32_t pack_h2(float a, float b) {
    __half2 h = __floats2half2_rn(a, b);
    return *(uint32_t*)&h;
}
__device__ __forceinline__ uint32_t pack2h(__half a, __half b) {
    __half2 h = __halves2half2(a, b);
    return *(uint32_t*)&h;
}

// Warp-level fp16 MMA: D(16x8,f32) += A(16x16,f16) * B(16x8,f16), row.col
__device__ __forceinline__ void mma_f16(float c[4],
                                        uint32_t a0, uint32_t a1, uint32_t a2, uint32_t a3,
                                        uint32_t b0, uint32_t b1) {
    asm volatile(
        "mma.sync.aligned.m16n8k16.row.col.f32.f16.f16.f32 "
        "{%0,%1,%2,%3}, {%4,%5,%6,%7}, {%8,%9}, {%0,%1,%2,%3};"
        : "+f"(c[0]), "+f"(c[1]), "+f"(c[2]), "+f"(c[3])
        : "r"(a0), "r"(a1), "r"(a2), "r"(a3), "r"(b0), "r"(b1));
}

// ---------------------------------------------------------------------------
// Kernel 0a: split weights to hi/lo fp16
// ---------------------------------------------------------------------------
__global__ __launch_bounds__(256) void convert_w_kernel(const float* __restrict__ wqkv,
                                                        const float* __restrict__ wout) {
    int i = blockIdx.x * 256 + threadIdx.x;
    const int NW = 3 * INNER * CC;
    if (i < NW) {
        float v = wqkv[i];
        __half h = __float2half_rn(v);
        g_wh[i] = h;
        g_wl[i] = __float2half_rn(v - __half2float(h));
    } else {
        int j = i - NW;
        if (j < CC * INNER) {
            float v = wout[j];
            __half h = __float2half_rn(v);
            g_woh[j] = h;
            g_wol[j] = __float2half_rn(v - __half2float(h));
        }
    }
}

// ---------------------------------------------------------------------------
// Kernel 0b: transpose + split x: [b][c][n] fp32 -> [b][n][c] hi/lo fp16
// ---------------------------------------------------------------------------
__global__ __launch_bounds__(256) void convert_x_kernel(const float* __restrict__ x) {
    __shared__ float sm[32][33];
    const int nt = blockIdx.x, ct = blockIdx.y, b = blockIdx.z;
    const int tx = threadIdx.x & 31, ty = threadIdx.x >> 5;

    const float* xb = x + ((size_t)b * CC + ct * 32) * N_TOK + nt * 32;
#pragma unroll
    for (int k = 0; k < 4; k++)
        sm[ty + k * 8][tx] = xb[(size_t)(ty + k * 8) * N_TOK + tx];
    __syncthreads();

#pragma unroll
    for (int k = 0; k < 4; k++) {
        int nl = ty + k * 8;
        float v = sm[tx][nl];
        __half h = __float2half_rn(v);
        size_t idx = ((size_t)b * N_TOK + nt * 32 + nl) * CC + ct * 32 + tx;
        g_xh[idx] = h;
        g_xl[idx] = __float2half_rn(v - __half2float(h));
    }
}

// ---------------------------------------------------------------------------
// Kernel A: QKV projection via split-fp16 mma (3-term), double-buffered.
// C[n][o] = xT[n][c] . W[o][c]^T. CTA: 128 tokens x 64 o. Fused l2norm.
// ---------------------------------------------------------------------------
#define QPADC 72
// per-stage layout (halfs): XH 128*72, XL 128*72, WH 64*72, WL 64*72
#define QXH_OFF 0
#define QXL_OFF (128 * QPADC)
#define QWH_OFF (2 * 128 * QPADC)
#define QWL_OFF (2 * 128 * QPADC + 64 * QPADC)
#define QSTAGE_H (2 * 128 * QPADC + 2 * 64 * QPADC)   // 27648 halfs
#define QSMEM_BYTES (2 * QSTAGE_H * 2)                // 110592 B
#define PADT 136

extern __shared__ char qkv_smem[];
__global__ __launch_bounds__(256, 2) void qkv_mma_kernel() {
    const int nt = blockIdx.x;      // 0..17
    const int oy = blockIdx.y;      // 0..23
    const int b  = blockIdx.z;
    const int n0 = nt * 128;
    const int o0 = oy * 64;
    const int p  = oy >> 3;
    const int h  = oy & 7;

    const int t    = threadIdx.x;
    const int lane = t & 31;
    const int wid  = t >> 5;
    const int r    = lane >> 2;
    const int cl   = lane & 3;
    const int qrow = wid * 16 + r;

    // loaders
    const int xrow = t >> 1, xseg = (t & 1) * 32;
    const int wrow = t >> 2, wseg = (t & 3) * 16;
    const __half* Xh = g_xh + ((size_t)b * N_TOK + n0 + xrow) * CC + xseg;
    const __half* Xl = g_xl + ((size_t)b * N_TOK + n0 + xrow) * CC + xseg;
    const __half* Wh = g_wh + (size_t)(o0 + wrow) * CC + wseg;
    const __half* Wl = g_wl + (size_t)(o0 + wrow) * CC + wseg;

    const uint32_t sbase = smem_u32(qkv_smem);
    const uint32_t xdh = sbase + (QXH_OFF + xrow * QPADC + xseg) * 2;
    const uint32_t xdl = sbase + (QXL_OFF + xrow * QPADC + xseg) * 2;
    const uint32_t wdh = sbase + (QWH_OFF + wrow * QPADC + wseg) * 2;
    const uint32_t wdl = sbase + (QWL_OFF + wrow * QPADC + wseg) * 2;

    float acc[8][4] = {};

    // prologue: stage 0
    {
#pragma unroll
        for (int k = 0; k < 4; k++) {
            cp16(xdh + k * 16, Xh + k * 8);
            cp16(xdl + k * 16, Xl + k * 8);
        }
        cp16(wdh, Wh);      cp16(wdh + 16, Wh + 8);
        cp16(wdl, Wl);      cp16(wdl + 16, Wl + 8);
        CP_COMMIT();
    }

    for (int it = 0; it < 4; it++) {
        const uint32_t stB = (uint32_t)(it & 1) * (QSTAGE_H * 2);
        CP_WAIT0();
        __syncthreads();

        if (it < 3) {
            const int c1 = (it + 1) * 64;
            const uint32_t nsB = (uint32_t)((it + 1) & 1) * (QSTAGE_H * 2);
#pragma unroll
            for (int k = 0; k < 4; k++) {
                cp16(xdh + nsB + k * 16, Xh + c1 + k * 8);
                cp16(xdl + nsB + k * 16, Xl + c1 + k * 8);
            }
            cp16(wdh + nsB, Wh + c1);      cp16(wdh + nsB + 16, Wh + c1 + 8);
            cp16(wdl + nsB, Wl + c1);      cp16(wdl + nsB + 16, Wl + c1 + 8);
            CP_COMMIT();
        }

        const __half* sXh = (const __half*)(qkv_smem + stB) + QXH_OFF;
        const __half* sXl = (const __half*)(qkv_smem + stB) + QXL_OFF;
        const __half* sWh = (const __half*)(qkv_smem + stB) + QWH_OFF;
        const __half* sWl = (const __half*)(qkv_smem + stB) + QWL_OFF;

#pragma unroll
        for (int kc = 0; kc < 4; kc++) {
            uint32_t ah[4], al[4];
            ah[0] = *(uint32_t*)&sXh[qrow * QPADC + kc * 16 + 2 * cl];
            ah[1] = *(uint32_t*)&sXh[(qrow + 8) * QPADC + kc * 16 + 2 * cl];
            ah[2] = *(uint32_t*)&sXh[qrow * QPADC + kc * 16 + 2 * cl + 8];
            ah[3] = *(uint32_t*)&sXh[(qrow + 8) * QPADC + kc * 16 + 2 * cl + 8];
            al[0] = *(uint32_t*)&sXl[qrow * QPADC + kc * 16 + 2 * cl];
            al[1] = *(uint32_t*)&sXl[(qrow + 8) * QPADC + kc * 16 + 2 * cl];
            al[2] = *(uint32_t*)&sXl[qrow * QPADC + kc * 16 + 2 * cl + 8];
            al[3] = *(uint32_t*)&sXl[(qrow + 8) * QPADC + kc * 16 + 2 * cl + 8];
#pragma unroll
            for (int ob = 0; ob < 8; ob++) {
                uint32_t bh0 = *(uint32_t*)&sWh[(ob * 8 + r) * QPADC + kc * 16 + 2 * cl];
                uint32_t bh1 = *(uint32_t*)&sWh[(ob * 8 + r) * QPADC + kc * 16 + 2 * cl + 8];
                uint32_t bl0 = *(uint32_t*)&sWl[(ob * 8 + r) * QPADC + kc * 16 + 2 * cl];
                uint32_t bl1 = *(uint32_t*)&sWl[(ob * 8 + r) * QPADC + kc * 16 + 2 * cl + 8];
                mma_f16(acc[ob], ah[0], ah[1], ah[2], ah[3], bh0, bh1);
                mma_f16(acc[ob], ah[0], ah[1], ah[2], ah[3], bl0, bl1);
                mma_f16(acc[ob], al[0], al[1], al[2], al[3], bh0, bh1);
            }
        }
    }

    const int bh = b * HEADS + h;

    if (p == 2) {
        // V: transpose via smem (half) then coalesced writes to g_vT [d][n]
        __half* sVt = (__half*)qkv_smem;   // [64][PADT]
        __syncthreads();
#pragma unroll
        for (int ob = 0; ob < 8; ob++) {
            int d = ob * 8 + 2 * cl;
            sVt[d * PADT + qrow]           = __float2half_rn(acc[ob][0]);
            sVt[(d + 1) * PADT + qrow]     = __float2half_rn(acc[ob][1]);
            sVt[d * PADT + qrow + 8]       = __float2half_rn(acc[ob][2]);
            sVt[(d + 1) * PADT + qrow + 8] = __float2half_rn(acc[ob][3]);
        }
        __syncthreads();
        const int d = t >> 2, seg = (t & 3) * 32;
        const uint4* src = (const uint4*)&sVt[d * PADT + seg];
        __half* dst = g_vT + ((size_t)bh * DH + d) * N_TOK + n0 + seg;
#pragma unroll
        for (int k = 0; k < 4; k++)
            *(uint4*)&dst[k * 8] = src[k];
    } else {
        // l2norm per token row (in-thread over 8 ob + quad shuffle)
        float l0 = 0.0f, l1 = 0.0f;
#pragma unroll
        for (int ob = 0; ob < 8; ob++) {
            l0 += acc[ob][0] * acc[ob][0] + acc[ob][1] * acc[ob][1];
            l1 += acc[ob][2] * acc[ob][2] + acc[ob][3] * acc[ob][3];
        }
        l0 += __shfl_xor_sync(0xffffffffu, l0, 1);
        l0 += __shfl_xor_sync(0xffffffffu, l0, 2);
        l1 += __shfl_xor_sync(0xffffffffu, l1, 1);
        l1 += __shfl_xor_sync(0xffffffffu, l1, 2);
        const float sf = (p == 0) ? QSCALE : 1.0f;   // fold SCALE*log2e into Q
        const float inv0 = sf / fmaxf(sqrtf(l0), 1e-12f);
        const float inv1 = sf / fmaxf(sqrtf(l1), 1e-12f);

        __half* dstb = (p == 0 ? g_qh : g_kh) + ((size_t)bh * N_TOK + n0) * DH;
#pragma unroll
        for (int ob = 0; ob < 8; ob++) {
            *(uint32_t*)&dstb[(size_t)qrow * DH + ob * 8 + 2 * cl] =
                pack_h2(acc[ob][0] * inv0, acc[ob][1] * inv0);
            *(uint32_t*)&dstb[(size_t)(qrow + 8) * DH + ob * 8 + 2 * cl] =
                pack_h2(acc[ob][2] * inv1, acc[ob][3] * inv1);
        }
    }
}

// ---------------------------------------------------------------------------
// Kernel B: fp16 m16n8k16 mma flash attention, cp.async double-buffered K/V.
// p = exp2(s - 10*log2e): Q pre-scaled by 10*log2e -> single MUFU.EX2.
// ---------------------------------------------------------------------------
#define PADH 72
#define KBUFB (64 * PADH * 2)
#define SK0B  0
#define SK1B  (KBUFB)
#define SVT0B (2 * KBUFB)
#define SVT1B (3 * KBUFB)
#define SQB   (4 * KBUFB)
#define ATT_SMEM_BYTES (4 * KBUFB + 128 * PADH * 2)
#define PADP 68
#define NKT (N_TOK / 64)

extern __shared__ char att_smem[];
__global__ __launch_bounds__(256, 2) void attn_mma_kernel() {
    __half* sQ = (__half*)(att_smem + SQB);
    float*  sO = (float*)att_smem;            // overlays K/VT buffers (post-loop)

    const int t    = threadIdx.x;
    const int lane = t & 31;
    const int wid  = t >> 5;
    const int qt   = blockIdx.x;
    const int h    = blockIdx.y;
    const int b    = blockIdx.z;
    const int bh   = b * HEADS + h;
    const int n0   = qt * 128;

    const int r  = lane >> 2;
    const int cl = lane & 3;
    const int qrow = wid * 16 + r;

    const int kvr = t >> 2;
    const int cw  = t & 3;
    const __half* Kgb = g_kh + ((size_t)bh * N_TOK + kvr) * DH + cw * 16;
    const __half* Vgb = g_vT + ((size_t)bh * DH + kvr) * N_TOK + cw * 16;

    const uint32_t sbase = smem_u32(att_smem);
    const uint32_t kdst[2] = { sbase + SK0B  + (kvr * PADH + cw * 16) * 2u,
                               sbase + SK1B  + (kvr * PADH + cw * 16) * 2u };
    const uint32_t vdst[2] = { sbase + SVT0B + (kvr * PADH + cw * 16) * 2u,
                               sbase + SVT1B + (kvr * PADH + cw * 16) * 2u };

    cp16(kdst[0], Kgb);      cp16(kdst[0] + 16, Kgb + 8);
    cp16(vdst[0], Vgb);      cp16(vdst[0] + 16, Vgb + 8);
    CP_COMMIT();
    {
        int row = t >> 1, cc = (t & 1) * 32;
        const uint4* src = (const uint4*)(g_qh + ((size_t)bh * N_TOK + n0 + row) * DH + cc);
        uint4* dst = (uint4*)(sQ + row * PADH + cc);
#pragma unroll
        for (int c = 0; c < 4; c++) dst[c] = src[c];
    }
    __syncthreads();

    uint32_t qa[4][4];
#pragma unroll
    for (int kb = 0; kb < 4; kb++) {
        qa[kb][0] = *(uint32_t*)&sQ[qrow * PADH + kb * 16 + 2 * cl];
        qa[kb][1] = *(uint32_t*)&sQ[(qrow + 8) * PADH + kb * 16 + 2 * cl];
        qa[kb][2] = *(uint32_t*)&sQ[qrow * PADH + kb * 16 + 2 * cl + 8];
        qa[kb][3] = *(uint32_t*)&sQ[(qrow + 8) * PADH + kb * 16 + 2 * cl + 8];
    }

    float o[8][4] = {};
    float l0 = 0.0f, l1 = 0.0f;

    for (int it = 0; it < NKT; it++) {
        const int buf = it & 1;
        CP_WAIT0();
        __syncthreads();

        if (it + 1 < NKT) {
            const __half* Kg = Kgb + (size_t)(it + 1) * 64 * DH;
            const __half* Vg = Vgb + (it + 1) * 64;
            const int nb2 = buf ^ 1;
            cp16(kdst[nb2], Kg);      cp16(kdst[nb2] + 16, Kg + 8);
            cp16(vdst[nb2], Vg);      cp16(vdst[nb2] + 16, Vg + 8);
            CP_COMMIT();
        }

        const __half* sK  = (const __half*)(att_smem + (buf ? SK1B : SK0B));
        const __half* sVT = (const __half*)(att_smem + (buf ? SVT1B : SVT0B));

        float s[8][4];
#pragma unroll
        for (int nb = 0; nb < 8; nb++) {
            s[nb][0] = s[nb][1] = s[nb][2] = s[nb][3] = 0.0f;
#pragma unroll
            for (int kb = 0; kb < 4; kb++) {
                uint32_t b0 = *(uint32_t*)&sK[(nb * 8 + r) * PADH + kb * 16 + 2 * cl];
                uint32_t b1 = *(uint32_t*)&sK[(nb * 8 + r) * PADH + kb * 16 + 2 * cl + 8];
                mma_f16(s[nb], qa[kb][0], qa[kb][1], qa[kb][2], qa[kb][3], b0, b1);
            }
        }

        uint32_t ph[8][2];
#pragma unroll
        for (int nb = 0; nb < 8; nb++) {
            float p0 = exp2f(s[nb][0] - QSCALE);
            float p1 = exp2f(s[nb][1] - QSCALE);
            float p2 = exp2f(s[nb][2] - QSCALE);
            float p3 = exp2f(s[nb][3] - QSCALE);
            l0 += p0 + p1;
            l1 += p2 + p3;
            ph[nb][0] = pack_h2(p0, p1);
            ph[nb][1] = pack_h2(p2, p3);
        }

#pragma unroll
        for (int kb = 0; kb < 4; kb++) {
            uint32_t a0 = ph[2 * kb][0];
            uint32_t a1 = ph[2 * kb][1];
            uint32_t a2 = ph[2 * kb + 1][0];
            uint32_t a3 = ph[2 * kb + 1][1];
#pragma unroll
            for (int nb = 0; nb < 8; nb++) {
                uint32_t b0 = *(uint32_t*)&sVT[(nb * 8 + r) * PADH + kb * 16 + 2 * cl];
                uint32_t b1 = *(uint32_t*)&sVT[(nb * 8 + r) * PADH + kb * 16 + 2 * cl + 8];
                mma_f16(o[nb], a0, a1, a2, a3, b0, b1);
            }
        }
    }

    l0 += __shfl_xor_sync(0xffffffffu, l0, 1);
    l0 += __shfl_xor_sync(0xffffffffu, l0, 2);
    l1 += __shfl_xor_sync(0xffffffffu, l1, 1);
    l1 += __shfl_xor_sync(0xffffffffu, l1, 2);
    const float inv0 = 1.0f / l0;
    const float inv1 = 1.0f / l1;

    __syncthreads();   // done reading K/VT buffers (sO overlays them)
#pragma unroll
    for (int nb = 0; nb < 8; nb++) {
        *(float2*)&sO[qrow * PADP + nb * 8 + 2 * cl] =
            make_float2(o[nb][0] * inv0, o[nb][1] * inv0);
        *(float2*)&sO[(qrow + 8) * PADP + nb * 8 + 2 * cl] =
            make_float2(o[nb][2] * inv1, o[nb][3] * inv1);
    }
    __syncthreads();

    // write O as hi/lo halves: g_ah/g_al [b][n0+row][h*64 + d]
    {
        const int row = t >> 1;
        const int seg = (t & 1) * 32;
        const float* src = sO + row * PADP + seg;
        const size_t base = ((size_t)b * N_TOK + n0 + row) * INNER + h * DH + seg;
#pragma unroll
        for (int c4 = 0; c4 < 4; c4++) {
            uint32_t uh[4], ul[4];
#pragma unroll
            for (int j = 0; j < 4; j++) {
                float v0 = src[c4 * 8 + 2 * j];
                float v1 = src[c4 * 8 + 2 * j + 1];
                __half h0 = __float2half_rn(v0);
                __half h1 = __float2half_rn(v1);
                uh[j] = pack2h(h0, h1);
                ul[j] = pack_h2(v0 - __half2float(h0), v1 - __half2float(h1));
            }
            *(uint4*)&g_ah[base + c4 * 8] = make_uint4(uh[0], uh[1], uh[2], uh[3]);
            *(uint4*)&g_al[base + c4 * 8] = make_uint4(ul[0], ul[1], ul[2], ul[3]);
        }
    }
}

// ---------------------------------------------------------------------------
// Kernel C: output projection via split-fp16 mma (3-term), double-buffered.
// out[o][n] = wout[o][ci] . G[n][ci]^T + bias. CTA: 64 o x 128 n, K=512.
// ---------------------------------------------------------------------------
extern __shared__ char out_smem[];
__global__ __launch_bounds__(256, 2) void out_mma_kernel(const float* __restrict__ bias,
                                                         float* __restrict__ out) {
    const int nt = blockIdx.x;   // 0..17
    const int ot = blockIdx.y;   // 0..3
    const int b  = blockIdx.z;
    const int n0 = nt * 128;
    const int o0 = ot * 64;

    const int t    = threadIdx.x;
    const int lane = t & 31;
    const int wid  = t >> 5;
    const int wo   = wid & 3;
    const int wn   = wid >> 2;
    const int r    = lane >> 2;
    const int cl   = lane & 3;
    const int orow = wo * 16 + r;

    const int grow = t >> 1, gseg = (t & 1) * 32;
    const int wrow = t >> 2, wseg = (t & 3) * 16;
    const __half* Gh = g_ah + ((size_t)b * N_TOK + n0 + grow) * INNER + gseg;
    const __half* Gl = g_al + ((size_t)b * N_TOK + n0 + grow) * INNER + gseg;
    const __half* Wh = g_woh + (size_t)(o0 + wrow) * INNER + wseg;
    const __half* Wl = g_wol + (size_t)(o0 + wrow) * INNER + wseg;

    const uint32_t sbase = smem_u32(out_smem);
    const uint32_t gdh = sbase + (QXH_OFF + grow * QPADC + gseg) * 2;
    const uint32_t gdl = sbase + (QXL_OFF + grow * QPADC + gseg) * 2;
    const uint32_t wdh = sbase + (QWH_OFF + wrow * QPADC + wseg) * 2;
    const uint32_t wdl = sbase + (QWL_OFF + wrow * QPADC + wseg) * 2;

    float acc[8][4] = {};

    // prologue: stage 0
    {
#pragma unroll
        for (int k = 0; k < 4; k++) {
            cp16(gdh + k * 16, Gh + k * 8);
            cp16(gdl + k * 16, Gl + k * 8);
        }
        cp16(wdh, Wh);      cp16(wdh + 16, Wh + 8);
        cp16(wdl, Wl);      cp16(wdl + 16, Wl + 8);
        CP_COMMIT();
    }

    for (int it = 0; it < 8; it++) {
        const uint32_t stB = (uint32_t)(it & 1) * (QSTAGE_H * 2);
        CP_WAIT0();
        __syncthreads();

        if (it < 7) {
            const int c1 = (it + 1) * 64;
            const uint32_t nsB = (uint32_t)((it + 1) & 1) * (QSTAGE_H * 2);
#pragma unroll
            for (int k = 0; k < 4; k++) {
                cp16(gdh + nsB + k * 16, Gh + c1 + k * 8);
                cp16(gdl + nsB + k * 16, Gl + c1 + k * 8);
            }
            cp16(wdh + nsB, Wh + c1);      cp16(wdh + nsB + 16, Wh + c1 + 8);
            cp16(wdl + nsB, Wl + c1);      cp16(wdl + nsB + 16, Wl + c1 + 8);
            CP_COMMIT();
        }

        const __half* sGh = (const __half*)(out_smem + stB) + QXH_OFF;
        const __half* sGl = (const __half*)(out_smem + stB) + QXL_OFF;
        const __half* sWh = (const __half*)(out_smem + stB) + QWH_OFF;
        const __half* sWl = (const __half*)(out_smem + stB) + QWL_OFF;

#pragma unroll
        for (int kc = 0; kc < 4; kc++) {
            uint32_t ah[4], al[4];
            ah[0] = *(uint32_t*)&sWh[orow * QPADC + kc * 16 + 2 * cl];
            ah[1] = *(uint32_t*)&sWh[(orow + 8) * QPADC + kc * 16 + 2 * cl];
            ah[2] = *(uint32_t*)&sWh[orow * QPADC + kc * 16 + 2 * cl + 8];
            ah[3] = *(uint32_t*)&sWh[(orow + 8) * QPADC + kc * 16 + 2 * cl + 8];
            al[0] = *(uint32_t*)&sWl[orow * QPADC + kc * 16 + 2 * cl];
            al[1] = *(uint32_t*)&sWl[(orow + 8) * QPADC + kc * 16 + 2 * cl];
            al[2] = *(uint32_t*)&sWl[orow * QPADC + kc * 16 + 2 * cl + 8];
            al[3] = *(uint32_t*)&sWl[(orow + 8) * QPADC + kc * 16 + 2 * cl + 8];
#pragma unroll
            for (int nb = 0; nb < 8; nb++) {
                int gn = wn * 64 + nb * 8 + r;
                uint32_t bh0 = *(uint32_t*)&sGh[gn * QPADC + kc * 16 + 2 * cl];
                uint32_t bh1 = *(uint32_t*)&sGh[gn * QPADC + kc * 16 + 2 * cl + 8];
                uint32_t bl0 = *(uint32_t*)&sGl[gn * QPADC + kc * 16 + 2 * cl];
                uint32_t bl1 = *(uint32_t*)&sGl[gn * QPADC + kc * 16 + 2 * cl + 8];
                mma_f16(acc[nb], ah[0], ah[1], ah[2], ah[3], bh0, bh1);
                mma_f16(acc[nb], ah[0], ah[1], ah[2], ah[3], bl0, bl1);
                mma_f16(acc[nb], al[0], al[1], al[2], al[3], bh0, bh1);
            }
        }
    }

    const int o_g = o0 + orow;
    const float bi0 = bias[o_g];
    const float bi1 = bias[o_g + 8];
    float* ob0 = out + ((size_t)b * CC + o_g) * N_TOK + n0 + wn * 64;
    float* ob1 = ob0 + 8 * N_TOK;
#pragma unroll
    for (int nb = 0; nb < 8; nb++) {
        *(float2*)&ob0[nb * 8 + 2 * cl] = make_float2(acc[nb][0] + bi0, acc[nb][1] + bi0);
        *(float2*)&ob1[nb * 8 + 2 * cl] = make_float2(acc[nb][2] + bi1, acc[nb][3] + bi1);
    }
}

// ---------------------------------------------------------------------------
extern "C" void kernel_launch(void* const* d_in, const int* in_sizes, int n_in,
                              void* d_out, int out_size) {
    const float* x    = (const float*)d_in[0];
    const float* wqkv = (const float*)d_in[1];
    const float* wout = (const float*)d_in[2];
    const float* bout = (const float*)d_in[3];
    float* out = (float*)d_out;

    (void)in_sizes; (void)n_in; (void)out_size;

    cudaFuncSetAttribute(qkv_mma_kernel, cudaFuncAttributeMaxDynamicSharedMemorySize,
                         QSMEM_BYTES);
    cudaFuncSetAttribute(attn_mma_kernel, cudaFuncAttributeMaxDynamicSharedMemorySize,
                         ATT_SMEM_BYTES);
    cudaFuncSetAttribute(out_mma_kernel, cudaFuncAttributeMaxDynamicSharedMemorySize,
                         QSMEM_BYTES);

    convert_w_kernel<<<(3 * INNER * CC + CC * INNER) / 256, 256>>>(wqkv, wout);
    convert_x_kernel<<<dim3(N_TOK / 32, CC / 32, BATCH), 256>>>(x);
    qkv_mma_kernel<<<dim3(18, 24, 4), 256, QSMEM_BYTES>>>();
    attn_mma_kernel<<<dim3(18, 8, 4), 256, ATT_SMEM_BYTES>>>();
    out_mma_kernel<<<dim3(18, 4, 4), 256, QSMEM_BYTES>>>(bout, out);
}